// round 13
// baseline (speedup 1.0000x reference)
#include <cuda_runtime.h>
#include <cstdint>

#define HORIZON 30
#define INDIM   384
#define BMAX    65536

typedef unsigned long long ull;

// gi_base scratch, TRANSPOSED layout: [row = gate*256 + j][B] fp32 (192 MB).
__device__ float g_gi[(size_t)768 * BMAX];

__device__ __forceinline__ ull pack2(float lo, float hi) {
    ull r; asm("mov.b64 %0, {%1, %2};" : "=l"(r) : "f"(lo), "f"(hi)); return r;
}
__device__ __forceinline__ void ffma2(ull& d, ull a, ull b) {
    asm("fma.rn.f32x2 %0, %1, %2, %0;" : "+l"(d) : "l"(a), "l"(b));
}
__device__ __forceinline__ void add2(ull& d, ull a) {
    asm("add.rn.f32x2 %0, %0, %1;" : "+l"(d) : "l"(a));
}
__device__ __forceinline__ void unpack2(ull v, float& lo, float& hi) {
    asm("mov.b64 {%0, %1}, %2;" : "=f"(lo), "=f"(hi) : "l"(v));
}
__device__ __forceinline__ float sigf(float x) {
    return __fdividef(1.f, 1.f + __expf(-x));
}
__device__ __forceinline__ float tanh_fast(float x) {
    float t = __expf(2.f * x);
    return 1.f - __fdividef(2.f, t + 1.f);
}
__device__ __forceinline__ void cpa16(uint32_t s, const void* g) {
    asm volatile("cp.async.cg.shared.global [%0], [%1], 16;" :: "r"(s), "l"(g));
}
#define CPA_COMMIT() asm volatile("cp.async.commit_group;")
#define CPA_WAIT1()  asm volatile("cp.async.wait_group 1;")
#define CPA_WAIT0()  asm volatile("cp.async.wait_group 0;")

// ---------------- shared memory layout (floats) ----------------
// h rows: 64 floats data + 4-float gap after m=31; stride 68.
#define HT_STRIDE 68
#define HT_SIZE   (256 * HT_STRIDE)          // 17408
#define OFF_HT    0                           // 2 ping-pong buffers
#define OFF_W     (2 * HT_SIZE)              // 34816
#define W_ROWPAD  20
#define WARP_WBUF (48 * W_ROWPAD)            // 960 floats: 48 rows x 16 k
#define W_REGION  (8 * 2 * WARP_WBUF)        // 15360 floats
#define OFF_WMUX  (OFF_W + W_REGION)         // 50176
#define OFF_WMUY  (OFF_WMUX + 768)
#define OFF_BHH   (OFF_WMUY + 768)
#define OFF_W5    (OFF_BHH + 768)
#define OFF_MUX   (OFF_W5 + 1280)
#define OFF_MUY   (OFF_MUX + 64)
#define SMEM_FLOATS (OFF_MUY + 64)           // 53888 floats = 215552 B

#define NTHR 256

__device__ __forceinline__ int mgap(int m) { return m + ((m >> 5) << 2); }

// Per-warp private W staging. Warp owns 16 j per jb (x3 gates = 48 rows).
// Buffer row = g*16 + j2*4 + grp  holds Whh row (g*256 + jb*128 + warp*16 + grp*4 + j2).
__device__ __forceinline__ void issue_chunk_w(uint32_t s_w_u32, const float* __restrict__ Whh,
                                              int c, int warp, int lane) {
    const int jb = (c >> 4) & 1;
    const int kc = c & 15;
    const uint32_t sbuf = s_w_u32 + (uint32_t)((warp * 2 + (c & 1)) * WARP_WBUF * 4);
    #pragma unroll
    for (int o = 0; o < 6; ++o) {
        int t = o * 32 + lane;            // 192 tasks: 48 rows x 4 quads
        int r = t >> 2, q = t & 3;
        int g = r >> 4, rl = r & 15;
        int jloc = (rl & 3) * 4 + (rl >> 2);
        const float* gp = Whh + (size_t)(g * 256 + jb * 128 + warp * 16 + jloc) * 256
                              + kc * 16 + q * 4;
        cpa16(sbuf + (uint32_t)((r * W_ROWPAD + q * 4) * 4), gp);
    }
}

__global__ void __launch_bounds__(NTHR, 1)
gru_decoder_kernel(const float* __restrict__ zh,  const float* __restrict__ Wh0,
                   const float* __restrict__ bh0, const float* __restrict__ Wih,
                   const float* __restrict__ bih, const float* __restrict__ Whh,
                   const float* __restrict__ bhhg,const float* __restrict__ Wmu,
                   const float* __restrict__ bmu, const float* __restrict__ Wcov,
                   const float* __restrict__ bcov,float* __restrict__ out, int B)
{
    extern __shared__ float sm[];
    float* s_w    = sm + OFF_W;
    float* s_wmux = sm + OFF_WMUX;
    float* s_wmuy = sm + OFF_WMUY;
    float* s_bhh  = sm + OFF_BHH;
    float* s_w5   = sm + OFF_W5;
    float* s_mux  = sm + OFF_MUX;
    float* s_muy  = sm + OFF_MUY;

    const int tid  = threadIdx.x;
    const int warp = tid >> 5, lane = tid & 31;
    const int wjb  = warp & 1;                // jb-stagger parity
    const int grp  = lane >> 3;               // 0..3: j-group within warp slice
    const int m0   = (lane & 7) * 8;          // 8 batch rows (4 f32x2 pairs)
    const int m0p  = mgap(m0);
    const int b0   = blockIdx.x * 64;
    const size_t Bs = (size_t)B;

    const uint32_t s_w_u32 = (uint32_t)__cvta_generic_to_shared(s_w);

    // ---- one-time small-weight staging ----
    for (int i = tid; i < 768; i += NTHR) {
        s_wmux[i] = Wih[(size_t)i * 386 + 384];
        s_wmuy[i] = Wih[(size_t)i * 386 + 385];
        s_bhh[i]  = bhhg[i];
    }
    for (int i = tid; i < 512; i += NTHR) s_w5[i] = Wmu[i];
    for (int i = tid; i < 768; i += NTHR) s_w5[512 + i] = Wcov[i];
    if (tid < 64) { s_mux[tid] = 0.f; s_muy[tid] = 0.f; }

    // ================= PRECOMPUTE: h0 (buf 0, gapped transposed) and gi_base ==========
    {
        const int tx4 = tid & 15, ty4 = tid >> 4;   // 16 x 16
        const int j04 = tx4 * 4, m04 = ty4 * 4;
        const int m04p = mgap(m04);
        float* s_zhT = s_w;          // [64 k][68]
        float* s_wtp = s_w + 4352;   // [64 k][68]

        for (int jb = 0; jb < 16; ++jb) {
            ull acc[4][2];
            #pragma unroll
            for (int m = 0; m < 4; ++m) { acc[m][0] = 0ull; acc[m][1] = 0ull; }

            for (int kc = 0; kc < 6; ++kc) {
                __syncthreads();
                #pragma unroll
                for (int it = 0; it < 16; ++it) {
                    int idx = it * NTHR + tid;
                    int kk = idx & 63, rr = idx >> 6;
                    s_zhT[kk * 68 + rr] = zh[(size_t)(b0 + rr) * INDIM + kc * 64 + kk];
                    int jp = jb * 64 + rr;
                    const float* wrow = (jp < 256) ? (Wh0 + (size_t)jp * 384)
                                                   : (Wih + (size_t)(jp - 256) * 386);
                    s_wtp[kk * 68 + rr] = wrow[kc * 64 + kk];
                }
                __syncthreads();
                #pragma unroll 8
                for (int k = 0; k < 64; ++k) {
                    float4 hv = *(const float4*)&s_zhT[k * 68 + m04];
                    ull w0 = *(const ull*)&s_wtp[k * 68 + j04];
                    ull w1 = *(const ull*)&s_wtp[k * 68 + j04 + 2];
                    ull a0 = pack2(hv.x, hv.x), a1 = pack2(hv.y, hv.y);
                    ull a2 = pack2(hv.z, hv.z), a3 = pack2(hv.w, hv.w);
                    ffma2(acc[0][0], a0, w0); ffma2(acc[0][1], a0, w1);
                    ffma2(acc[1][0], a1, w0); ffma2(acc[1][1], a1, w1);
                    ffma2(acc[2][0], a2, w0); ffma2(acc[2][1], a2, w1);
                    ffma2(acc[3][0], a3, w0); ffma2(acc[3][1], a3, w1);
                }
            }
            float v[4][4];
            #pragma unroll
            for (int m = 0; m < 4; ++m) {
                unpack2(acc[m][0], v[m][0], v[m][1]);
                unpack2(acc[m][1], v[m][2], v[m][3]);
            }
            if (jb < 4) {
                #pragma unroll
                for (int jj = 0; jj < 4; ++jj) {
                    int j = jb * 64 + j04 + jj;
                    float b = bh0[j];
                    *(float4*)&sm[OFF_HT + (size_t)j * HT_STRIDE + m04p] =
                        make_float4(v[0][jj] + b, v[1][jj] + b, v[2][jj] + b, v[3][jj] + b);
                }
            } else {
                int gcol = jb * 64 - 256 + j04;
                float4 bb = *(const float4*)&bih[gcol];
                const float* bbp = (const float*)&bb;
                #pragma unroll
                for (int jj = 0; jj < 4; ++jj) {
                    *(float4*)&g_gi[(size_t)(gcol + jj) * Bs + b0 + m04] =
                        make_float4(v[0][jj] + bbp[jj], v[1][jj] + bbp[jj],
                                    v[2][jj] + bbp[jj], v[3][jj] + bbp[jj]);
                }
            }
        }
        __syncthreads();    // precompute done before W staging reuses s_w
    }

    const size_t covbase = (size_t)B * HORIZON * 2;

    // Prime per-warp W pipeline with this warp's first two chunks (its own jb order)
    issue_chunk_w(s_w_u32, Whh, wjb * 16 + 0, warp, lane);
    CPA_COMMIT();
    issue_chunk_w(s_w_u32, Whh, wjb * 16 + 1, warp, lane);
    CPA_COMMIT();

    // ================= 30-step GRU recurrence =================
    int cur = 0;
    #pragma unroll 1
    for (int t = 0; t < HORIZON; ++t) {
        float* hcur = sm + OFF_HT + cur * HT_SIZE;
        float* hnxt = sm + OFF_HT + (1 - cur) * HT_SIZE;

        #pragma unroll 1
        for (int jbi = 0; jbi < 2; ++jbi) {
            const int jb  = jbi ^ wjb;                         // staggered jb order
            const int jg0 = jb * 128 + warp * 16 + grp * 4;    // lane's 4 contiguous j

            // ---- acc init: r/z gates seeded with gi + b_hh + mu rank-2 terms;
            //      n gate seeded with b_hn only (r multiplies the hidden part). ----
            ull acc[3][4][4];
            {
                // mu pairs for this lane's 8 m (valid: barrier at end of prev step)
                ulonglong2 mxq0 = *(const ulonglong2*)&s_mux[m0];
                ulonglong2 mxq1 = *(const ulonglong2*)&s_mux[m0 + 4];
                ulonglong2 myq0 = *(const ulonglong2*)&s_muy[m0];
                ulonglong2 myq1 = *(const ulonglong2*)&s_muy[m0 + 4];
                ull mx[4] = {mxq0.x, mxq0.y, mxq1.x, mxq1.y};
                ull my[4] = {myq0.x, myq0.y, myq1.x, myq1.y};
                #pragma unroll
                for (int j2 = 0; j2 < 4; ++j2) {
                    const int j = jg0 + j2;
                    // L2 prefetch for the n-gate gi row used in the epilogue
                    asm volatile("prefetch.global.L2 [%0];"
                                 :: "l"(g_gi + (size_t)(512 + j) * Bs + b0 + m0));
                    // r gate
                    {
                        const float* p = g_gi + (size_t)j * Bs + b0 + m0;
                        ulonglong2 g0 = *(const ulonglong2*)p;
                        ulonglong2 g1 = *(const ulonglong2*)(p + 4);
                        float b = s_bhh[j];
                        ull bb = pack2(b, b);
                        ull wx = pack2(s_wmux[j], s_wmux[j]);
                        ull wy = pack2(s_wmuy[j], s_wmuy[j]);
                        ull a0 = g0.x, a1 = g0.y, a2 = g1.x, a3 = g1.y;
                        add2(a0, bb); add2(a1, bb); add2(a2, bb); add2(a3, bb);
                        ffma2(a0, mx[0], wx); ffma2(a1, mx[1], wx);
                        ffma2(a2, mx[2], wx); ffma2(a3, mx[3], wx);
                        ffma2(a0, my[0], wy); ffma2(a1, my[1], wy);
                        ffma2(a2, my[2], wy); ffma2(a3, my[3], wy);
                        acc[0][j2][0]=a0; acc[0][j2][1]=a1; acc[0][j2][2]=a2; acc[0][j2][3]=a3;
                    }
                    // z gate
                    {
                        const float* p = g_gi + (size_t)(256 + j) * Bs + b0 + m0;
                        ulonglong2 g0 = *(const ulonglong2*)p;
                        ulonglong2 g1 = *(const ulonglong2*)(p + 4);
                        float b = s_bhh[256 + j];
                        ull bb = pack2(b, b);
                        ull wx = pack2(s_wmux[256 + j], s_wmux[256 + j]);
                        ull wy = pack2(s_wmuy[256 + j], s_wmuy[256 + j]);
                        ull a0 = g0.x, a1 = g0.y, a2 = g1.x, a3 = g1.y;
                        add2(a0, bb); add2(a1, bb); add2(a2, bb); add2(a3, bb);
                        ffma2(a0, mx[0], wx); ffma2(a1, mx[1], wx);
                        ffma2(a2, mx[2], wx); ffma2(a3, mx[3], wx);
                        ffma2(a0, my[0], wy); ffma2(a1, my[1], wy);
                        ffma2(a2, my[2], wy); ffma2(a3, my[3], wy);
                        acc[1][j2][0]=a0; acc[1][j2][1]=a1; acc[1][j2][2]=a2; acc[1][j2][3]=a3;
                    }
                    // n gate: bias only
                    {
                        float b = s_bhh[512 + j];
                        ull bb = pack2(b, b);
                        #pragma unroll
                        for (int mp = 0; mp < 4; ++mp) acc[2][j2][mp] = bb;
                    }
                }
            }

            #pragma unroll 1
            for (int kc = 0; kc < 16; ++kc) {
                CPA_WAIT1();   // sequence element (jbi*16+kc) resident in buffer (kc&1)

                const float* wb  = s_w + (warp * 2 + (kc & 1)) * WARP_WBUF;
                const float* hch = hcur + (size_t)(kc * 16) * HT_STRIDE + m0p;

                #pragma unroll
                for (int kg = 0; kg < 4; ++kg) {
                    float4 w4[3][4];
                    #pragma unroll
                    for (int g = 0; g < 3; ++g)
                        #pragma unroll
                        for (int j2 = 0; j2 < 4; ++j2)
                            w4[g][j2] = *(const float4*)
                                &wb[(g * 16 + j2 * 4 + grp) * W_ROWPAD + kg * 4];
                    #pragma unroll
                    for (int kk = 0; kk < 4; ++kk) {
                        const float* hr = hch + (size_t)(kg * 4 + kk) * HT_STRIDE;
                        ulonglong2 q0 = *(const ulonglong2*)hr;        // m pairs 0..1
                        ulonglong2 q1 = *(const ulonglong2*)(hr + 4);  // m pairs 2..3
                        #pragma unroll
                        for (int g = 0; g < 3; ++g)
                            #pragma unroll
                            for (int j2 = 0; j2 < 4; ++j2) {
                                float ws = ((const float*)&w4[g][j2])[kk];
                                ull d = pack2(ws, ws);
                                ffma2(acc[g][j2][0], q0.x, d);
                                ffma2(acc[g][j2][1], q0.y, d);
                                ffma2(acc[g][j2][2], q1.x, d);
                                ffma2(acc[g][j2][3], q1.y, d);
                            }
                    }
                }
                // Issue sequence element s+2 (wraps into next step's identical order).
                {
                    int s2 = jbi * 16 + kc + 2;                 // up to 33
                    int jb2 = ((s2 >> 4) & 1) ^ wjb;
                    int c2  = jb2 * 16 + (s2 & 15);
                    issue_chunk_w(s_w_u32, Whh, c2, warp, lane);
                    CPA_COMMIT();
                }
            }

            // ---- gate epilogue: fr/fz are complete pre-activations now ----
            #pragma unroll
            for (int j2 = 0; j2 < 4; ++j2) {
                const int j = jg0 + j2;
                float fr[8], fz[8], fn[8];
                #pragma unroll
                for (int mp = 0; mp < 4; ++mp) {
                    unpack2(acc[0][j2][mp], fr[2*mp], fr[2*mp+1]);
                    unpack2(acc[1][j2][mp], fz[2*mp], fz[2*mp+1]);
                    unpack2(acc[2][j2][mp], fn[2*mp], fn[2*mp+1]);
                }
                const float* pn = g_gi + (size_t)(512 + j) * Bs + b0 + m0;
                float4 gn0 = *(const float4*)pn, gn1 = *(const float4*)(pn + 4);
                float gN[8] = {gn0.x,gn0.y,gn0.z,gn0.w, gn1.x,gn1.y,gn1.z,gn1.w};

                float wxn = s_wmux[512 + j];
                float wyn = s_wmuy[512 + j];

                const float* hp = &hcur[(size_t)j * HT_STRIDE + m0p];
                float4 o0 = *(const float4*)hp;
                float4 o1 = *(const float4*)(hp + 4);
                float ho[8] = {o0.x,o0.y,o0.z,o0.w,o1.x,o1.y,o1.z,o1.w};

                float hnew[8];
                #pragma unroll
                for (int m = 0; m < 8; ++m) {
                    float mx = s_mux[m0 + m], my = s_muy[m0 + m];
                    float r  = sigf(fr[m]);
                    float z  = sigf(fz[m]);
                    float n  = tanh_fast(gN[m] + mx * wxn + my * wyn + r * fn[m]);
                    hnew[m] = (1.f - z) * n + z * ho[m];
                }
                float* hq = &hnxt[(size_t)j * HT_STRIDE + m0p];
                *(float4*)hq       = make_float4(hnew[0], hnew[1], hnew[2], hnew[3]);
                *(float4*)(hq + 4) = make_float4(hnew[4], hnew[5], hnew[6], hnew[7]);
            }
        } // jbi

        __syncthreads();   // hnxt complete (both jb halves, all warps)

        // ---- mu / cov: 5 outputs x 32 m-pairs = 160 tasks, float2 column loads ----
        if (tid < 160) {
            int o = tid >> 5; int mp = tid & 31;
            int m = mp * 2;
            const float* wrow = &s_w5[o * 256];
            const float* hc = hnxt + mgap(m);
            float2 A0 = make_float2(0.f, 0.f), A1 = make_float2(0.f, 0.f);
            float2 A2 = make_float2(0.f, 0.f), A3 = make_float2(0.f, 0.f);
            #pragma unroll 4
            for (int k = 0; k < 256; k += 4) {
                float2 v0 = *(const float2*)&hc[(size_t)(k    ) * HT_STRIDE];
                float2 v1 = *(const float2*)&hc[(size_t)(k + 1) * HT_STRIDE];
                float2 v2 = *(const float2*)&hc[(size_t)(k + 2) * HT_STRIDE];
                float2 v3 = *(const float2*)&hc[(size_t)(k + 3) * HT_STRIDE];
                A0.x += v0.x * wrow[k    ];  A0.y += v0.y * wrow[k    ];
                A1.x += v1.x * wrow[k + 1];  A1.y += v1.y * wrow[k + 1];
                A2.x += v2.x * wrow[k + 2];  A2.y += v2.y * wrow[k + 2];
                A3.x += v3.x * wrow[k + 3];  A3.y += v3.y * wrow[k + 3];
            }
            float accA = (A0.x + A1.x) + (A2.x + A3.x);
            float accB = (A0.y + A1.y) + (A2.y + A3.y);
            #pragma unroll
            for (int h2 = 0; h2 < 2; ++h2) {
                float acc5 = h2 ? accB : accA;
                int mm = m + h2;
                size_t idx2 = ((size_t)(b0 + mm) * HORIZON + t);
                if (o == 0) {
                    float vv = acc5 + bmu[0]; out[idx2 * 2]     = vv; s_mux[mm] = vv;
                } else if (o == 1) {
                    float vv = acc5 + bmu[1]; out[idx2 * 2 + 1] = vv; s_muy[mm] = vv;
                } else if (o == 2) {
                    float vv = fminf(fmaxf(acc5 + bcov[0], 0.2f), 1.0f);
                    out[covbase + idx2 * 4]     = vv;
                } else if (o == 3) {
                    float vv = fminf(fmaxf(acc5 + bcov[1], -0.1f), 0.1f);
                    out[covbase + idx2 * 4 + 1] = vv;
                    out[covbase + idx2 * 4 + 2] = vv;
                } else {
                    float vv = fminf(fmaxf(acc5 + bcov[2], 0.2f), 1.0f);
                    out[covbase + idx2 * 4 + 3] = vv;
                }
            }
        }
        __syncthreads();   // s_mux/s_muy published before next step's acc init reads
        cur ^= 1;
    }

    CPA_WAIT0();   // drain speculative prefetches
}

extern "C" void kernel_launch(void* const* d_in, const int* in_sizes, int n_in,
                              void* d_out, int out_size) {
    const float* zh   = (const float*)d_in[0];
    const float* Wh0  = (const float*)d_in[1];
    const float* bh0  = (const float*)d_in[2];
    const float* Wih  = (const float*)d_in[3];
    const float* bih  = (const float*)d_in[4];
    const float* Whh  = (const float*)d_in[5];
    const float* bhh  = (const float*)d_in[6];
    const float* Wmu  = (const float*)d_in[7];
    const float* bmu  = (const float*)d_in[8];
    const float* Wcov = (const float*)d_in[9];
    const float* bcov = (const float*)d_in[10];
    float* out = (float*)d_out;

    int B = in_sizes[0] / INDIM;
    cudaFuncSetAttribute(gru_decoder_kernel,
                         cudaFuncAttributeMaxDynamicSharedMemorySize, SMEM_FLOATS * 4);
    gru_decoder_kernel<<<B / 64, NTHR, SMEM_FLOATS * 4>>>(
        zh, Wh0, bh0, Wih, bih, Whh, bhh, Wmu, bmu, Wcov, bcov, out, B);
}

// round 14
// speedup vs baseline: 1.0618x; 1.0618x over previous
#include <cuda_runtime.h>
#include <cstdint>

#define HORIZON 30
#define INDIM   384
#define BMAX    65536

typedef unsigned long long ull;

// gi_base scratch, TRANSPOSED layout: [row = gate*256 + j][B] fp32 (192 MB).
__device__ float g_gi[(size_t)768 * BMAX];

__device__ __forceinline__ ull pack2(float lo, float hi) {
    ull r; asm("mov.b64 %0, {%1, %2};" : "=l"(r) : "f"(lo), "f"(hi)); return r;
}
__device__ __forceinline__ void ffma2(ull& d, ull a, ull b) {
    asm("fma.rn.f32x2 %0, %1, %2, %0;" : "+l"(d) : "l"(a), "l"(b));
}
__device__ __forceinline__ void unpack2(ull v, float& lo, float& hi) {
    asm("mov.b64 {%0, %1}, %2;" : "=f"(lo), "=f"(hi) : "l"(v));
}
__device__ __forceinline__ float sigf(float x) {
    return __fdividef(1.f, 1.f + __expf(-x));
}
__device__ __forceinline__ float tanh_fast(float x) {
    float t = __expf(2.f * x);
    return 1.f - __fdividef(2.f, t + 1.f);
}
__device__ __forceinline__ void cpa16(uint32_t s, const void* g) {
    asm volatile("cp.async.cg.shared.global [%0], [%1], 16;" :: "r"(s), "l"(g));
}
#define CPA_COMMIT() asm volatile("cp.async.commit_group;")
#define CPA_WAIT1()  asm volatile("cp.async.wait_group 1;")
#define CPA_WAIT0()  asm volatile("cp.async.wait_group 0;")

// ---------------- shared memory layout (floats) ----------------
// h rows: 64 floats of data with a 4-float gap after m=31; stride 72.
#define HT_STRIDE 72
#define HT_SIZE   (256 * HT_STRIDE)          // 18432
#define OFF_HT    0                           // 2 ping-pong buffers
#define OFF_W     (2 * HT_SIZE)              // 36864
#define W_ROWPAD  20
#define WARP_WBUF (48 * W_ROWPAD)            // 960 floats: 48 rows x 16 k
#define W_REGION  (8 * 2 * WARP_WBUF)        // 15360 floats (8 warps x 2 buffers)
#define OFF_WMUX  (OFF_W + W_REGION)         // 52224
#define OFF_WMUY  (OFF_WMUX + 768)
#define OFF_BHH   (OFF_WMUY + 768)
#define OFF_W5    (OFF_BHH + 768)
#define OFF_MUX   (OFF_W5 + 1280)
#define OFF_MUY   (OFF_MUX + 64)
#define SMEM_FLOATS (OFF_MUY + 64)           // 55936 floats = 223744 B

#define NTHR 256

__device__ __forceinline__ int mgap(int m) { return m + ((m >> 5) << 2); }

// Per-warp private W staging. Warp owns 16 j per jb (x3 gates = 48 rows).
// Buffer row = g*16 + j2*4 + grp  holds Whh row (g*256 + jb*128 + warp*16 + grp*4 + j2).
__device__ __forceinline__ void issue_chunk_w(uint32_t s_w_u32, const float* __restrict__ Whh,
                                              int c, int warp, int lane) {
    const int jb = (c >> 4) & 1;
    const int kc = c & 15;
    const uint32_t sbuf = s_w_u32 + (uint32_t)((warp * 2 + (c & 1)) * WARP_WBUF * 4);
    #pragma unroll
    for (int o = 0; o < 6; ++o) {
        int t = o * 32 + lane;            // 192 tasks: 48 rows x 4 quads
        int r = t >> 2, q = t & 3;        // r: buffer row 0..47
        int g = r >> 4, rl = r & 15;
        int jloc = (rl & 3) * 4 + (rl >> 2);   // inverse of row permutation
        const float* gp = Whh + (size_t)(g * 256 + jb * 128 + warp * 16 + jloc) * 256
                              + kc * 16 + q * 4;
        cpa16(sbuf + (uint32_t)((r * W_ROWPAD + q * 4) * 4), gp);
    }
}

__global__ void __launch_bounds__(NTHR, 1)
gru_decoder_kernel(const float* __restrict__ zh,  const float* __restrict__ Wh0,
                   const float* __restrict__ bh0, const float* __restrict__ Wih,
                   const float* __restrict__ bih, const float* __restrict__ Whh,
                   const float* __restrict__ bhhg,const float* __restrict__ Wmu,
                   const float* __restrict__ bmu, const float* __restrict__ Wcov,
                   const float* __restrict__ bcov,float* __restrict__ out, int B)
{
    extern __shared__ float sm[];
    float* s_w    = sm + OFF_W;
    float* s_wmux = sm + OFF_WMUX;
    float* s_wmuy = sm + OFF_WMUY;
    float* s_bhh  = sm + OFF_BHH;
    float* s_w5   = sm + OFF_W5;
    float* s_mux  = sm + OFF_MUX;
    float* s_muy  = sm + OFF_MUY;

    const int tid  = threadIdx.x;
    const int warp = tid >> 5, lane = tid & 31;
    const int wjb  = warp & 1;                // jb-stagger parity
    const int grp  = lane >> 3;               // 0..3: j-group within warp slice
    const int m0   = (lane & 7) * 8;          // 8 batch rows (4 f32x2 pairs)
    const int m0p  = mgap(m0);
    const int b0   = blockIdx.x * 64;
    const size_t Bs = (size_t)B;

    const uint32_t s_w_u32 = (uint32_t)__cvta_generic_to_shared(s_w);

    // ---- one-time small-weight staging ----
    for (int i = tid; i < 768; i += NTHR) {
        s_wmux[i] = Wih[(size_t)i * 386 + 384];
        s_wmuy[i] = Wih[(size_t)i * 386 + 385];
        s_bhh[i]  = bhhg[i];
    }
    for (int i = tid; i < 512; i += NTHR) s_w5[i] = Wmu[i];
    for (int i = tid; i < 768; i += NTHR) s_w5[512 + i] = Wcov[i];
    if (tid < 64) { s_mux[tid] = 0.f; s_muy[tid] = 0.f; }

    // ================= PRECOMPUTE: h0 (buf 0, gapped transposed) and gi_base ==========
    {
        const int tx4 = tid & 15, ty4 = tid >> 4;   // 16 x 16
        const int j04 = tx4 * 4, m04 = ty4 * 4;     // j-tile 4, m-tile 4
        const int m04p = mgap(m04);                  // m04 mult of 4: no gap crossing
        float* s_zhT = s_w;          // [64 k][68]
        float* s_wtp = s_w + 4352;   // [64 k][68]

        for (int jb = 0; jb < 16; ++jb) {
            ull acc[4][2];
            #pragma unroll
            for (int m = 0; m < 4; ++m) { acc[m][0] = 0ull; acc[m][1] = 0ull; }

            for (int kc = 0; kc < 6; ++kc) {
                __syncthreads();
                #pragma unroll
                for (int it = 0; it < 16; ++it) {
                    int idx = it * NTHR + tid;
                    int kk = idx & 63, rr = idx >> 6;
                    s_zhT[kk * 68 + rr] = zh[(size_t)(b0 + rr) * INDIM + kc * 64 + kk];
                    int jp = jb * 64 + rr;
                    const float* wrow = (jp < 256) ? (Wh0 + (size_t)jp * 384)
                                                   : (Wih + (size_t)(jp - 256) * 386);
                    s_wtp[kk * 68 + rr] = wrow[kc * 64 + kk];
                }
                __syncthreads();
                #pragma unroll 8
                for (int k = 0; k < 64; ++k) {
                    float4 hv = *(const float4*)&s_zhT[k * 68 + m04];
                    ull w0 = *(const ull*)&s_wtp[k * 68 + j04];
                    ull w1 = *(const ull*)&s_wtp[k * 68 + j04 + 2];
                    ull a0 = pack2(hv.x, hv.x), a1 = pack2(hv.y, hv.y);
                    ull a2 = pack2(hv.z, hv.z), a3 = pack2(hv.w, hv.w);
                    ffma2(acc[0][0], a0, w0); ffma2(acc[0][1], a0, w1);
                    ffma2(acc[1][0], a1, w0); ffma2(acc[1][1], a1, w1);
                    ffma2(acc[2][0], a2, w0); ffma2(acc[2][1], a2, w1);
                    ffma2(acc[3][0], a3, w0); ffma2(acc[3][1], a3, w1);
                }
            }
            float v[4][4];
            #pragma unroll
            for (int m = 0; m < 4; ++m) {
                unpack2(acc[m][0], v[m][0], v[m][1]);
                unpack2(acc[m][1], v[m][2], v[m][3]);
            }
            if (jb < 4) {
                #pragma unroll
                for (int jj = 0; jj < 4; ++jj) {
                    int j = jb * 64 + j04 + jj;
                    float b = bh0[j];
                    *(float4*)&sm[OFF_HT + (size_t)j * HT_STRIDE + m04p] =
                        make_float4(v[0][jj] + b, v[1][jj] + b, v[2][jj] + b, v[3][jj] + b);
                }
            } else {
                int gcol = jb * 64 - 256 + j04;
                float4 bb = *(const float4*)&bih[gcol];
                const float* bbp = (const float*)&bb;
                #pragma unroll
                for (int jj = 0; jj < 4; ++jj) {
                    *(float4*)&g_gi[(size_t)(gcol + jj) * Bs + b0 + m04] =
                        make_float4(v[0][jj] + bbp[jj], v[1][jj] + bbp[jj],
                                    v[2][jj] + bbp[jj], v[3][jj] + bbp[jj]);
                }
            }
        }
        __syncthreads();    // precompute done before W staging reuses s_w
    }

    const size_t covbase = (size_t)B * HORIZON * 2;

    // Prime per-warp W pipeline with this warp's first two chunks (its own jb order)
    issue_chunk_w(s_w_u32, Whh, wjb * 16 + 0, warp, lane);
    CPA_COMMIT();
    issue_chunk_w(s_w_u32, Whh, wjb * 16 + 1, warp, lane);
    CPA_COMMIT();

    // ================= 30-step GRU recurrence (R7 barrier scheme) =================
    int cur = 0;
    #pragma unroll 1
    for (int t = 0; t < HORIZON; ++t) {
        float* hcur = sm + OFF_HT + cur * HT_SIZE;
        float* hnxt = sm + OFF_HT + (1 - cur) * HT_SIZE;

        #pragma unroll 1
        for (int jbi = 0; jbi < 2; ++jbi) {
            const int jb  = jbi ^ wjb;                         // staggered jb order
            const int jg0 = jb * 128 + warp * 16 + grp * 4;    // lane's 4 contiguous j

            // acc[gate][j2][mpair], seeded with b_hh
            ull acc[3][4][4];
            #pragma unroll
            for (int g = 0; g < 3; ++g)
                #pragma unroll
                for (int j2 = 0; j2 < 4; ++j2) {
                    float b = s_bhh[g * 256 + jg0 + j2];
                    ull bb = pack2(b, b);
                    #pragma unroll
                    for (int mp = 0; mp < 4; ++mp) acc[g][j2][mp] = bb;
                }

            // Dependency-free L2 warm-up for the epilogue's 12 gi rows.
            // Nothing reads these results; the epilogue LDGs hit warm L2/L1.
            #pragma unroll
            for (int j2 = 0; j2 < 4; ++j2) {
                const int j = jg0 + j2;
                asm volatile("prefetch.global.L2 [%0];"
                             :: "l"(g_gi + (size_t)(        j) * Bs + b0 + m0));
                asm volatile("prefetch.global.L2 [%0];"
                             :: "l"(g_gi + (size_t)(256 +   j) * Bs + b0 + m0));
                asm volatile("prefetch.global.L2 [%0];"
                             :: "l"(g_gi + (size_t)(512 +   j) * Bs + b0 + m0));
            }

            #pragma unroll 1
            for (int kc = 0; kc < 16; ++kc) {
                CPA_WAIT1();   // sequence element (jbi*16+kc) resident in buffer (kc&1)

                const float* wb  = s_w + (warp * 2 + (kc & 1)) * WARP_WBUF;
                const float* hch = hcur + (size_t)(kc * 16) * HT_STRIDE + m0p;

                #pragma unroll
                for (int kg = 0; kg < 4; ++kg) {
                    // 12 LDS.128: W quads for (3 gates x 4 j2), conflict-free rows
                    float4 w4[3][4];
                    #pragma unroll
                    for (int g = 0; g < 3; ++g)
                        #pragma unroll
                        for (int j2 = 0; j2 < 4; ++j2)
                            w4[g][j2] = *(const float4*)
                                &wb[(g * 16 + j2 * 4 + grp) * W_ROWPAD + kg * 4];
                    #pragma unroll
                    for (int kk = 0; kk < 4; ++kk) {
                        const float* hr = hch + (size_t)(kg * 4 + kk) * HT_STRIDE;
                        ulonglong2 q0 = *(const ulonglong2*)hr;        // m pairs 0..1
                        ulonglong2 q1 = *(const ulonglong2*)(hr + 4);  // m pairs 2..3
                        #pragma unroll
                        for (int g = 0; g < 3; ++g)
                            #pragma unroll
                            for (int j2 = 0; j2 < 4; ++j2) {
                                float ws = ((const float*)&w4[g][j2])[kk];
                                ull d = pack2(ws, ws);
                                ffma2(acc[g][j2][0], q0.x, d);
                                ffma2(acc[g][j2][1], q0.y, d);
                                ffma2(acc[g][j2][2], q1.x, d);
                                ffma2(acc[g][j2][3], q1.y, d);
                            }
                    }
                }
                // Issue sequence element s+2 (wraps into next step's identical order).
                {
                    int s2 = jbi * 16 + kc + 2;                 // up to 33
                    int jb2 = ((s2 >> 4) & 1) ^ wjb;
                    int c2  = jb2 * 16 + (s2 & 15);
                    issue_chunk_w(s_w_u32, Whh, c2, warp, lane);
                    CPA_COMMIT();
                }
            }

            // ---- gate epilogue: 4 j x 8 m GRU cells (per j2 to bound reg pressure) ----
            #pragma unroll
            for (int j2 = 0; j2 < 4; ++j2) {
                const int j = jg0 + j2;
                float fr[8], fz[8], fn[8];
                #pragma unroll
                for (int mp = 0; mp < 4; ++mp) {
                    unpack2(acc[0][j2][mp], fr[2*mp], fr[2*mp+1]);
                    unpack2(acc[1][j2][mp], fz[2*mp], fz[2*mp+1]);
                    unpack2(acc[2][j2][mp], fn[2*mp], fn[2*mp+1]);
                }
                const float* pr = g_gi + (size_t)(        j) * Bs + b0 + m0;
                const float* pz = g_gi + (size_t)(256 +   j) * Bs + b0 + m0;
                const float* pn = g_gi + (size_t)(512 +   j) * Bs + b0 + m0;
                float4 gr0 = *(const float4*)pr,       gr1 = *(const float4*)(pr + 4);
                float4 gz0 = *(const float4*)pz,       gz1 = *(const float4*)(pz + 4);
                float4 gn0 = *(const float4*)pn,       gn1 = *(const float4*)(pn + 4);
                float gR[8] = {gr0.x,gr0.y,gr0.z,gr0.w, gr1.x,gr1.y,gr1.z,gr1.w};
                float gZ[8] = {gz0.x,gz0.y,gz0.z,gz0.w, gz1.x,gz1.y,gz1.z,gz1.w};
                float gN[8] = {gn0.x,gn0.y,gn0.z,gn0.w, gn1.x,gn1.y,gn1.z,gn1.w};

                float wxr = s_wmux[j], wxz = s_wmux[256 + j], wxn = s_wmux[512 + j];
                float wyr = s_wmuy[j], wyz = s_wmuy[256 + j], wyn = s_wmuy[512 + j];

                const float* hp = &hcur[(size_t)j * HT_STRIDE + m0p];
                float4 o0 = *(const float4*)hp;
                float4 o1 = *(const float4*)(hp + 4);
                float ho[8] = {o0.x,o0.y,o0.z,o0.w,o1.x,o1.y,o1.z,o1.w};

                float hnew[8];
                #pragma unroll
                for (int m = 0; m < 8; ++m) {
                    float mx = s_mux[m0 + m], my = s_muy[m0 + m];
                    float r  = sigf(gR[m] + mx * wxr + my * wyr + fr[m]);
                    float z  = sigf(gZ[m] + mx * wxz + my * wyz + fz[m]);
                    float n  = tanh_fast(gN[m] + mx * wxn + my * wyn + r * fn[m]);
                    hnew[m] = (1.f - z) * n + z * ho[m];
                }
                float* hq = &hnxt[(size_t)j * HT_STRIDE + m0p];
                *(float4*)hq       = make_float4(hnew[0], hnew[1], hnew[2], hnew[3]);
                *(float4*)(hq + 4) = make_float4(hnew[4], hnew[5], hnew[6], hnew[7]);
            }
        } // jbi

        __syncthreads();   // hnxt complete (both jb halves, all warps)

        // ---- mu / cov: 5 outputs x 32 m-pairs = 160 tasks, float2 column loads ----
        if (tid < 160) {
            int o = tid >> 5; int mp = tid & 31;
            int m = mp * 2;
            const float* wrow = &s_w5[o * 256];
            const float* hc = hnxt + mgap(m);
            float2 A0 = make_float2(0.f, 0.f), A1 = make_float2(0.f, 0.f);
            float2 A2 = make_float2(0.f, 0.f), A3 = make_float2(0.f, 0.f);
            #pragma unroll 4
            for (int k = 0; k < 256; k += 4) {
                float2 v0 = *(const float2*)&hc[(size_t)(k    ) * HT_STRIDE];
                float2 v1 = *(const float2*)&hc[(size_t)(k + 1) * HT_STRIDE];
                float2 v2 = *(const float2*)&hc[(size_t)(k + 2) * HT_STRIDE];
                float2 v3 = *(const float2*)&hc[(size_t)(k + 3) * HT_STRIDE];
                A0.x += v0.x * wrow[k    ];  A0.y += v0.y * wrow[k    ];
                A1.x += v1.x * wrow[k + 1];  A1.y += v1.y * wrow[k + 1];
                A2.x += v2.x * wrow[k + 2];  A2.y += v2.y * wrow[k + 2];
                A3.x += v3.x * wrow[k + 3];  A3.y += v3.y * wrow[k + 3];
            }
            float accA = (A0.x + A1.x) + (A2.x + A3.x);
            float accB = (A0.y + A1.y) + (A2.y + A3.y);
            #pragma unroll
            for (int h2 = 0; h2 < 2; ++h2) {
                float acc5 = h2 ? accB : accA;
                int mm = m + h2;
                size_t idx2 = ((size_t)(b0 + mm) * HORIZON + t);
                if (o == 0) {
                    float vv = acc5 + bmu[0]; out[idx2 * 2]     = vv; s_mux[mm] = vv;
                } else if (o == 1) {
                    float vv = acc5 + bmu[1]; out[idx2 * 2 + 1] = vv; s_muy[mm] = vv;
                } else if (o == 2) {
                    float vv = fminf(fmaxf(acc5 + bcov[0], 0.2f), 1.0f);
                    out[covbase + idx2 * 4]     = vv;
                } else if (o == 3) {
                    float vv = fminf(fmaxf(acc5 + bcov[1], -0.1f), 0.1f);
                    out[covbase + idx2 * 4 + 1] = vv;
                    out[covbase + idx2 * 4 + 2] = vv;
                } else {
                    float vv = fminf(fmaxf(acc5 + bcov[2], 0.2f), 1.0f);
                    out[covbase + idx2 * 4 + 3] = vv;
                }
            }
        }
        __syncthreads();   // s_mux/s_muy published before next step's epilogues read
        cur ^= 1;
    }

    CPA_WAIT0();   // drain speculative prefetches
}

extern "C" void kernel_launch(void* const* d_in, const int* in_sizes, int n_in,
                              void* d_out, int out_size) {
    const float* zh   = (const float*)d_in[0];
    const float* Wh0  = (const float*)d_in[1];
    const float* bh0  = (const float*)d_in[2];
    const float* Wih  = (const float*)d_in[3];
    const float* bih  = (const float*)d_in[4];
    const float* Whh  = (const float*)d_in[5];
    const float* bhh  = (const float*)d_in[6];
    const float* Wmu  = (const float*)d_in[7];
    const float* bmu  = (const float*)d_in[8];
    const float* Wcov = (const float*)d_in[9];
    const float* bcov = (const float*)d_in[10];
    float* out = (float*)d_out;

    int B = in_sizes[0] / INDIM;
    cudaFuncSetAttribute(gru_decoder_kernel,
                         cudaFuncAttributeMaxDynamicSharedMemorySize, SMEM_FLOATS * 4);
    gru_decoder_kernel<<<B / 64, NTHR, SMEM_FLOATS * 4>>>(
        zh, Wh0, bh0, Wih, bih, Whh, bhh, Wmu, bmu, Wcov, bcov, out, B);
}

// round 15
// speedup vs baseline: 1.0797x; 1.0168x over previous
#include <cuda_runtime.h>
#include <cstdint>

#define HORIZON 30
#define INDIM   384
#define BMAX    65536

typedef unsigned long long ull;

// gi_base scratch, TRANSPOSED layout: [row = gate*256 + j][B] fp32 (192 MB).
__device__ float g_gi[(size_t)768 * BMAX];

__device__ __forceinline__ ull pack2(float lo, float hi) {
    ull r; asm("mov.b64 %0, {%1, %2};" : "=l"(r) : "f"(lo), "f"(hi)); return r;
}
__device__ __forceinline__ void ffma2(ull& d, ull a, ull b) {
    asm("fma.rn.f32x2 %0, %1, %2, %0;" : "+l"(d) : "l"(a), "l"(b));
}
__device__ __forceinline__ void unpack2(ull v, float& lo, float& hi) {
    asm("mov.b64 {%0, %1}, %2;" : "=f"(lo), "=f"(hi) : "l"(v));
}
// Native 5th-gen MUFU tanh: 1 MUFU op, max err ~2^-11 (recurrence is
// contractive per R1-R13 evidence: output rel_err tracks single-application err).
__device__ __forceinline__ float tanha(float x) {
    float y; asm("tanh.approx.f32 %0, %1;" : "=f"(y) : "f"(x)); return y;
}
__device__ __forceinline__ float sig_t(float x) {
    return fmaf(0.5f, tanha(0.5f * x), 0.5f);
}
__device__ __forceinline__ void cpa16(uint32_t s, const void* g) {
    asm volatile("cp.async.cg.shared.global [%0], [%1], 16;" :: "r"(s), "l"(g));
}
#define CPA_COMMIT() asm volatile("cp.async.commit_group;")
#define CPA_WAIT1()  asm volatile("cp.async.wait_group 1;")
#define CPA_WAIT0()  asm volatile("cp.async.wait_group 0;")

// ---------------- shared memory layout (floats) ----------------
// h rows: 64 floats of data with a 4-float gap after m=31; stride 72.
#define HT_STRIDE 72
#define HT_SIZE   (256 * HT_STRIDE)          // 18432
#define OFF_HT    0                           // 2 ping-pong buffers
#define OFF_W     (2 * HT_SIZE)              // 36864
#define W_ROWPAD  20
#define WARP_WBUF (48 * W_ROWPAD)            // 960 floats: 48 rows x 16 k
#define W_REGION  (8 * 2 * WARP_WBUF)        // 15360 floats (8 warps x 2 buffers)
#define OFF_WMUX  (OFF_W + W_REGION)         // 52224
#define OFF_WMUY  (OFF_WMUX + 768)
#define OFF_BHH   (OFF_WMUY + 768)
#define OFF_W5    (OFF_BHH + 768)
#define OFF_MUX   (OFF_W5 + 1280)
#define OFF_MUY   (OFF_MUX + 64)
#define SMEM_FLOATS (OFF_MUY + 64)           // 55936 floats = 223744 B

#define NTHR 256

__device__ __forceinline__ int mgap(int m) { return m + ((m >> 5) << 2); }

// Per-warp private W staging. Warp owns 16 j per jb (x3 gates = 48 rows).
// Buffer row = g*16 + j2*4 + grp  holds Whh row (g*256 + jb*128 + warp*16 + grp*4 + j2).
__device__ __forceinline__ void issue_chunk_w(uint32_t s_w_u32, const float* __restrict__ Whh,
                                              int c, int warp, int lane) {
    const int jb = (c >> 4) & 1;
    const int kc = c & 15;
    const uint32_t sbuf = s_w_u32 + (uint32_t)((warp * 2 + (c & 1)) * WARP_WBUF * 4);
    #pragma unroll
    for (int o = 0; o < 6; ++o) {
        int t = o * 32 + lane;            // 192 tasks: 48 rows x 4 quads
        int r = t >> 2, q = t & 3;        // r: buffer row 0..47
        int g = r >> 4, rl = r & 15;
        int jloc = (rl & 3) * 4 + (rl >> 2);   // inverse of row permutation
        const float* gp = Whh + (size_t)(g * 256 + jb * 128 + warp * 16 + jloc) * 256
                              + kc * 16 + q * 4;
        cpa16(sbuf + (uint32_t)((r * W_ROWPAD + q * 4) * 4), gp);
    }
}

__global__ void __launch_bounds__(NTHR, 1)
gru_decoder_kernel(const float* __restrict__ zh,  const float* __restrict__ Wh0,
                   const float* __restrict__ bh0, const float* __restrict__ Wih,
                   const float* __restrict__ bih, const float* __restrict__ Whh,
                   const float* __restrict__ bhhg,const float* __restrict__ Wmu,
                   const float* __restrict__ bmu, const float* __restrict__ Wcov,
                   const float* __restrict__ bcov,float* __restrict__ out, int B)
{
    extern __shared__ float sm[];
    float* s_w    = sm + OFF_W;
    float* s_wmux = sm + OFF_WMUX;
    float* s_wmuy = sm + OFF_WMUY;
    float* s_bhh  = sm + OFF_BHH;
    float* s_w5   = sm + OFF_W5;
    float* s_mux  = sm + OFF_MUX;
    float* s_muy  = sm + OFF_MUY;

    const int tid  = threadIdx.x;
    const int warp = tid >> 5, lane = tid & 31;
    const int wjb  = warp & 1;                // jb-stagger parity
    const int grp  = lane >> 3;               // 0..3: j-group within warp slice
    const int m0   = (lane & 7) * 8;          // 8 batch rows (4 f32x2 pairs)
    const int m0p  = mgap(m0);
    const int b0   = blockIdx.x * 64;
    const size_t Bs = (size_t)B;

    const uint32_t s_w_u32 = (uint32_t)__cvta_generic_to_shared(s_w);

    // ---- one-time small-weight staging ----
    for (int i = tid; i < 768; i += NTHR) {
        s_wmux[i] = Wih[(size_t)i * 386 + 384];
        s_wmuy[i] = Wih[(size_t)i * 386 + 385];
        s_bhh[i]  = bhhg[i];
    }
    for (int i = tid; i < 512; i += NTHR) s_w5[i] = Wmu[i];
    for (int i = tid; i < 768; i += NTHR) s_w5[512 + i] = Wcov[i];
    if (tid < 64) { s_mux[tid] = 0.f; s_muy[tid] = 0.f; }

    // ================= PRECOMPUTE: h0 (buf 0, gapped transposed) and gi_base ==========
    {
        const int tx4 = tid & 15, ty4 = tid >> 4;   // 16 x 16
        const int j04 = tx4 * 4, m04 = ty4 * 4;     // j-tile 4, m-tile 4
        const int m04p = mgap(m04);                  // m04 mult of 4: no gap crossing
        float* s_zhT = s_w;          // [64 k][68]
        float* s_wtp = s_w + 4352;   // [64 k][68]

        for (int jb = 0; jb < 16; ++jb) {
            ull acc[4][2];
            #pragma unroll
            for (int m = 0; m < 4; ++m) { acc[m][0] = 0ull; acc[m][1] = 0ull; }

            for (int kc = 0; kc < 6; ++kc) {
                __syncthreads();
                #pragma unroll
                for (int it = 0; it < 16; ++it) {
                    int idx = it * NTHR + tid;
                    int kk = idx & 63, rr = idx >> 6;
                    s_zhT[kk * 68 + rr] = zh[(size_t)(b0 + rr) * INDIM + kc * 64 + kk];
                    int jp = jb * 64 + rr;
                    const float* wrow = (jp < 256) ? (Wh0 + (size_t)jp * 384)
                                                   : (Wih + (size_t)(jp - 256) * 386);
                    s_wtp[kk * 68 + rr] = wrow[kc * 64 + kk];
                }
                __syncthreads();
                #pragma unroll 8
                for (int k = 0; k < 64; ++k) {
                    float4 hv = *(const float4*)&s_zhT[k * 68 + m04];
                    ull w0 = *(const ull*)&s_wtp[k * 68 + j04];
                    ull w1 = *(const ull*)&s_wtp[k * 68 + j04 + 2];
                    ull a0 = pack2(hv.x, hv.x), a1 = pack2(hv.y, hv.y);
                    ull a2 = pack2(hv.z, hv.z), a3 = pack2(hv.w, hv.w);
                    ffma2(acc[0][0], a0, w0); ffma2(acc[0][1], a0, w1);
                    ffma2(acc[1][0], a1, w0); ffma2(acc[1][1], a1, w1);
                    ffma2(acc[2][0], a2, w0); ffma2(acc[2][1], a2, w1);
                    ffma2(acc[3][0], a3, w0); ffma2(acc[3][1], a3, w1);
                }
            }
            float v[4][4];
            #pragma unroll
            for (int m = 0; m < 4; ++m) {
                unpack2(acc[m][0], v[m][0], v[m][1]);
                unpack2(acc[m][1], v[m][2], v[m][3]);
            }
            if (jb < 4) {
                #pragma unroll
                for (int jj = 0; jj < 4; ++jj) {
                    int j = jb * 64 + j04 + jj;
                    float b = bh0[j];
                    *(float4*)&sm[OFF_HT + (size_t)j * HT_STRIDE + m04p] =
                        make_float4(v[0][jj] + b, v[1][jj] + b, v[2][jj] + b, v[3][jj] + b);
                }
            } else {
                int gcol = jb * 64 - 256 + j04;
                float4 bb = *(const float4*)&bih[gcol];
                const float* bbp = (const float*)&bb;
                #pragma unroll
                for (int jj = 0; jj < 4; ++jj) {
                    *(float4*)&g_gi[(size_t)(gcol + jj) * Bs + b0 + m04] =
                        make_float4(v[0][jj] + bbp[jj], v[1][jj] + bbp[jj],
                                    v[2][jj] + bbp[jj], v[3][jj] + bbp[jj]);
                }
            }
        }
        __syncthreads();    // precompute done before W staging reuses s_w
    }

    const size_t covbase = (size_t)B * HORIZON * 2;

    // Prime per-warp W pipeline with this warp's first two chunks (its own jb order)
    issue_chunk_w(s_w_u32, Whh, wjb * 16 + 0, warp, lane);
    CPA_COMMIT();
    issue_chunk_w(s_w_u32, Whh, wjb * 16 + 1, warp, lane);
    CPA_COMMIT();

    // ================= 30-step GRU recurrence (R7 barrier scheme) =================
    int cur = 0;
    #pragma unroll 1
    for (int t = 0; t < HORIZON; ++t) {
        float* hcur = sm + OFF_HT + cur * HT_SIZE;
        float* hnxt = sm + OFF_HT + (1 - cur) * HT_SIZE;

        #pragma unroll 1
        for (int jbi = 0; jbi < 2; ++jbi) {
            const int jb  = jbi ^ wjb;                         // staggered jb order
            const int jg0 = jb * 128 + warp * 16 + grp * 4;    // lane's 4 contiguous j

            // acc[gate][j2][mpair], seeded with b_hh
            ull acc[3][4][4];
            #pragma unroll
            for (int g = 0; g < 3; ++g)
                #pragma unroll
                for (int j2 = 0; j2 < 4; ++j2) {
                    float b = s_bhh[g * 256 + jg0 + j2];
                    ull bb = pack2(b, b);
                    #pragma unroll
                    for (int mp = 0; mp < 4; ++mp) acc[g][j2][mp] = bb;
                }

            // Dependency-free L2 warm-up for the epilogue's 12 gi rows.
            #pragma unroll
            for (int j2 = 0; j2 < 4; ++j2) {
                const int j = jg0 + j2;
                asm volatile("prefetch.global.L2 [%0];"
                             :: "l"(g_gi + (size_t)(        j) * Bs + b0 + m0));
                asm volatile("prefetch.global.L2 [%0];"
                             :: "l"(g_gi + (size_t)(256 +   j) * Bs + b0 + m0));
                asm volatile("prefetch.global.L2 [%0];"
                             :: "l"(g_gi + (size_t)(512 +   j) * Bs + b0 + m0));
            }

            #pragma unroll 1
            for (int kc = 0; kc < 16; ++kc) {
                CPA_WAIT1();   // sequence element (jbi*16+kc) resident in buffer (kc&1)

                const float* wb  = s_w + (warp * 2 + (kc & 1)) * WARP_WBUF;
                const float* hch = hcur + (size_t)(kc * 16) * HT_STRIDE + m0p;

                #pragma unroll
                for (int kg = 0; kg < 4; ++kg) {
                    // 12 LDS.128: W quads for (3 gates x 4 j2), conflict-free rows
                    float4 w4[3][4];
                    #pragma unroll
                    for (int g = 0; g < 3; ++g)
                        #pragma unroll
                        for (int j2 = 0; j2 < 4; ++j2)
                            w4[g][j2] = *(const float4*)
                                &wb[(g * 16 + j2 * 4 + grp) * W_ROWPAD + kg * 4];
                    #pragma unroll
                    for (int kk = 0; kk < 4; ++kk) {
                        const float* hr = hch + (size_t)(kg * 4 + kk) * HT_STRIDE;
                        ulonglong2 q0 = *(const ulonglong2*)hr;        // m pairs 0..1
                        ulonglong2 q1 = *(const ulonglong2*)(hr + 4);  // m pairs 2..3
                        #pragma unroll
                        for (int g = 0; g < 3; ++g)
                            #pragma unroll
                            for (int j2 = 0; j2 < 4; ++j2) {
                                float ws = ((const float*)&w4[g][j2])[kk];
                                ull d = pack2(ws, ws);
                                ffma2(acc[g][j2][0], q0.x, d);
                                ffma2(acc[g][j2][1], q0.y, d);
                                ffma2(acc[g][j2][2], q1.x, d);
                                ffma2(acc[g][j2][3], q1.y, d);
                            }
                    }
                }
                // Issue sequence element s+2 (wraps into next step's identical order).
                {
                    int s2 = jbi * 16 + kc + 2;                 // up to 33
                    int jb2 = ((s2 >> 4) & 1) ^ wjb;
                    int c2  = jb2 * 16 + (s2 & 15);
                    issue_chunk_w(s_w_u32, Whh, c2, warp, lane);
                    CPA_COMMIT();
                }
            }

            // ---- gate epilogue: 4 j x 8 m GRU cells (per j2 to bound reg pressure) ----
            #pragma unroll
            for (int j2 = 0; j2 < 4; ++j2) {
                const int j = jg0 + j2;
                float fr[8], fz[8], fn[8];
                #pragma unroll
                for (int mp = 0; mp < 4; ++mp) {
                    unpack2(acc[0][j2][mp], fr[2*mp], fr[2*mp+1]);
                    unpack2(acc[1][j2][mp], fz[2*mp], fz[2*mp+1]);
                    unpack2(acc[2][j2][mp], fn[2*mp], fn[2*mp+1]);
                }
                const float* pr = g_gi + (size_t)(        j) * Bs + b0 + m0;
                const float* pz = g_gi + (size_t)(256 +   j) * Bs + b0 + m0;
                const float* pn = g_gi + (size_t)(512 +   j) * Bs + b0 + m0;
                float4 gr0 = *(const float4*)pr,       gr1 = *(const float4*)(pr + 4);
                float4 gz0 = *(const float4*)pz,       gz1 = *(const float4*)(pz + 4);
                float4 gn0 = *(const float4*)pn,       gn1 = *(const float4*)(pn + 4);
                float gR[8] = {gr0.x,gr0.y,gr0.z,gr0.w, gr1.x,gr1.y,gr1.z,gr1.w};
                float gZ[8] = {gz0.x,gz0.y,gz0.z,gz0.w, gz1.x,gz1.y,gz1.z,gz1.w};
                float gN[8] = {gn0.x,gn0.y,gn0.z,gn0.w, gn1.x,gn1.y,gn1.z,gn1.w};

                float wxr = s_wmux[j], wxz = s_wmux[256 + j], wxn = s_wmux[512 + j];
                float wyr = s_wmuy[j], wyz = s_wmuy[256 + j], wyn = s_wmuy[512 + j];

                const float* hp = &hcur[(size_t)j * HT_STRIDE + m0p];
                float4 o0 = *(const float4*)hp;
                float4 o1 = *(const float4*)(hp + 4);
                float ho[8] = {o0.x,o0.y,o0.z,o0.w,o1.x,o1.y,o1.z,o1.w};

                float hnew[8];
                #pragma unroll
                for (int m = 0; m < 8; ++m) {
                    float mx = s_mux[m0 + m], my = s_muy[m0 + m];
                    float r  = sig_t(gR[m] + mx * wxr + my * wyr + fr[m]);
                    float z  = sig_t(gZ[m] + mx * wxz + my * wyz + fz[m]);
                    float n  = tanha(gN[m] + mx * wxn + my * wyn + r * fn[m]);
                    hnew[m] = (1.f - z) * n + z * ho[m];
                }
                float* hq = &hnxt[(size_t)j * HT_STRIDE + m0p];
                *(float4*)hq       = make_float4(hnew[0], hnew[1], hnew[2], hnew[3]);
                *(float4*)(hq + 4) = make_float4(hnew[4], hnew[5], hnew[6], hnew[7]);
            }
        } // jbi

        __syncthreads();   // hnxt complete (both jb halves, all warps)

        // ---- mu / cov: 5 outputs x 32 m-pairs = 160 tasks, float2 column loads ----
        if (tid < 160) {
            int o = tid >> 5; int mp = tid & 31;
            int m = mp * 2;
            const float* wrow = &s_w5[o * 256];
            const float* hc = hnxt + mgap(m);
            float2 A0 = make_float2(0.f, 0.f), A1 = make_float2(0.f, 0.f);
            float2 A2 = make_float2(0.f, 0.f), A3 = make_float2(0.f, 0.f);
            #pragma unroll 4
            for (int k = 0; k < 256; k += 4) {
                float2 v0 = *(const float2*)&hc[(size_t)(k    ) * HT_STRIDE];
                float2 v1 = *(const float2*)&hc[(size_t)(k + 1) * HT_STRIDE];
                float2 v2 = *(const float2*)&hc[(size_t)(k + 2) * HT_STRIDE];
                float2 v3 = *(const float2*)&hc[(size_t)(k + 3) * HT_STRIDE];
                A0.x += v0.x * wrow[k    ];  A0.y += v0.y * wrow[k    ];
                A1.x += v1.x * wrow[k + 1];  A1.y += v1.y * wrow[k + 1];
                A2.x += v2.x * wrow[k + 2];  A2.y += v2.y * wrow[k + 2];
                A3.x += v3.x * wrow[k + 3];  A3.y += v3.y * wrow[k + 3];
            }
            float accA = (A0.x + A1.x) + (A2.x + A3.x);
            float accB = (A0.y + A1.y) + (A2.y + A3.y);
            #pragma unroll
            for (int h2 = 0; h2 < 2; ++h2) {
                float acc5 = h2 ? accB : accA;
                int mm = m + h2;
                size_t idx2 = ((size_t)(b0 + mm) * HORIZON + t);
                if (o == 0) {
                    float vv = acc5 + bmu[0]; out[idx2 * 2]     = vv; s_mux[mm] = vv;
                } else if (o == 1) {
                    float vv = acc5 + bmu[1]; out[idx2 * 2 + 1] = vv; s_muy[mm] = vv;
                } else if (o == 2) {
                    float vv = fminf(fmaxf(acc5 + bcov[0], 0.2f), 1.0f);
                    out[covbase + idx2 * 4]     = vv;
                } else if (o == 3) {
                    float vv = fminf(fmaxf(acc5 + bcov[1], -0.1f), 0.1f);
                    out[covbase + idx2 * 4 + 1] = vv;
                    out[covbase + idx2 * 4 + 2] = vv;
                } else {
                    float vv = fminf(fmaxf(acc5 + bcov[2], 0.2f), 1.0f);
                    out[covbase + idx2 * 4 + 3] = vv;
                }
            }
        }
        __syncthreads();   // s_mux/s_muy published before next step's epilogues read
        cur ^= 1;
    }

    CPA_WAIT0();   // drain speculative prefetches
}

extern "C" void kernel_launch(void* const* d_in, const int* in_sizes, int n_in,
                              void* d_out, int out_size) {
    const float* zh   = (const float*)d_in[0];
    const float* Wh0  = (const float*)d_in[1];
    const float* bh0  = (const float*)d_in[2];
    const float* Wih  = (const float*)d_in[3];
    const float* bih  = (const float*)d_in[4];
    const float* Whh  = (const float*)d_in[5];
    const float* bhh  = (const float*)d_in[6];
    const float* Wmu  = (const float*)d_in[7];
    const float* bmu  = (const float*)d_in[8];
    const float* Wcov = (const float*)d_in[9];
    const float* bcov = (const float*)d_in[10];
    float* out = (float*)d_out;

    int B = in_sizes[0] / INDIM;
    cudaFuncSetAttribute(gru_decoder_kernel,
                         cudaFuncAttributeMaxDynamicSharedMemorySize, SMEM_FLOATS * 4);
    gru_decoder_kernel<<<B / 64, NTHR, SMEM_FLOATS * 4>>>(
        zh, Wh0, bh0, Wih, bih, Whh, bhh, Wmu, bmu, Wcov, bcov, out, B);
}

// round 16
// speedup vs baseline: 1.0867x; 1.0065x over previous
#include <cuda_runtime.h>
#include <cstdint>

#define HORIZON 30
#define INDIM   384
#define BMAX    65536

typedef unsigned long long ull;

// gi_base scratch, TRANSPOSED layout: [row = gate*256 + j][B] fp32 (192 MB).
__device__ float g_gi[(size_t)768 * BMAX];

__device__ __forceinline__ ull pack2(float lo, float hi) {
    ull r; asm("mov.b64 %0, {%1, %2};" : "=l"(r) : "f"(lo), "f"(hi)); return r;
}
__device__ __forceinline__ void ffma2(ull& d, ull a, ull b) {
    asm("fma.rn.f32x2 %0, %1, %2, %0;" : "+l"(d) : "l"(a), "l"(b));
}
__device__ __forceinline__ ull ffma2v(ull a, ull b, ull c) {
    ull d; asm("fma.rn.f32x2 %0, %1, %2, %3;" : "=l"(d) : "l"(a), "l"(b), "l"(c)); return d;
}
__device__ __forceinline__ ull add2v(ull a, ull b) {
    ull d; asm("add.rn.f32x2 %0, %1, %2;" : "=l"(d) : "l"(a), "l"(b)); return d;
}
__device__ __forceinline__ void unpack2(ull v, float& lo, float& hi) {
    asm("mov.b64 {%0, %1}, %2;" : "=f"(lo), "=f"(hi) : "l"(v));
}
// Native 5th-gen MUFU tanh: 1 MUFU op, max err ~2^-11 (recurrence contractive:
// measured output rel_err 4.1e-6 << 1e-3 threshold).
__device__ __forceinline__ float tanha(float x) {
    float y; asm("tanh.approx.f32 %0, %1;" : "=f"(y) : "f"(x)); return y;
}
__device__ __forceinline__ float sig_t(float x) {
    return fmaf(0.5f, tanha(0.5f * x), 0.5f);
}
__device__ __forceinline__ void cpa16(uint32_t s, const void* g) {
    asm volatile("cp.async.cg.shared.global [%0], [%1], 16;" :: "r"(s), "l"(g));
}
#define CPA_COMMIT() asm volatile("cp.async.commit_group;")
#define CPA_WAIT1()  asm volatile("cp.async.wait_group 1;")
#define CPA_WAIT0()  asm volatile("cp.async.wait_group 0;")

// ---------------- shared memory layout (floats) ----------------
// h rows: 64 floats of data with a 4-float gap after m=31; stride 72.
#define HT_STRIDE 72
#define HT_SIZE   (256 * HT_STRIDE)          // 18432
#define OFF_HT    0                           // 2 ping-pong buffers
#define OFF_W     (2 * HT_SIZE)              // 36864
#define W_ROWPAD  20
#define WARP_WBUF (48 * W_ROWPAD)            // 960 floats: 48 rows x 16 k
#define W_REGION  (8 * 2 * WARP_WBUF)        // 15360 floats (8 warps x 2 buffers)
#define OFF_WMUX  (OFF_W + W_REGION)         // 52224
#define OFF_WMUY  (OFF_WMUX + 768)
#define OFF_BHH   (OFF_WMUY + 768)
#define OFF_W5    (OFF_BHH + 768)
#define OFF_MUX   (OFF_W5 + 1280)
#define OFF_MUY   (OFF_MUX + 64)
#define SMEM_FLOATS (OFF_MUY + 64)           // 55936 floats = 223744 B

#define NTHR 256

__device__ __forceinline__ int mgap(int m) { return m + ((m >> 5) << 2); }

// Per-warp private W staging. Warp owns 16 j per jb (x3 gates = 48 rows).
// Buffer row = g*16 + j2*4 + grp  holds Whh row (g*256 + jb*128 + warp*16 + grp*4 + j2).
__device__ __forceinline__ void issue_chunk_w(uint32_t s_w_u32, const float* __restrict__ Whh,
                                              int c, int warp, int lane) {
    const int jb = (c >> 4) & 1;
    const int kc = c & 15;
    const uint32_t sbuf = s_w_u32 + (uint32_t)((warp * 2 + (c & 1)) * WARP_WBUF * 4);
    #pragma unroll
    for (int o = 0; o < 6; ++o) {
        int t = o * 32 + lane;            // 192 tasks: 48 rows x 4 quads
        int r = t >> 2, q = t & 3;        // r: buffer row 0..47
        int g = r >> 4, rl = r & 15;
        int jloc = (rl & 3) * 4 + (rl >> 2);   // inverse of row permutation
        const float* gp = Whh + (size_t)(g * 256 + jb * 128 + warp * 16 + jloc) * 256
                              + kc * 16 + q * 4;
        cpa16(sbuf + (uint32_t)((r * W_ROWPAD + q * 4) * 4), gp);
    }
}

__global__ void __launch_bounds__(NTHR, 1)
gru_decoder_kernel(const float* __restrict__ zh,  const float* __restrict__ Wh0,
                   const float* __restrict__ bh0, const float* __restrict__ Wih,
                   const float* __restrict__ bih, const float* __restrict__ Whh,
                   const float* __restrict__ bhhg,const float* __restrict__ Wmu,
                   const float* __restrict__ bmu, const float* __restrict__ Wcov,
                   const float* __restrict__ bcov,float* __restrict__ out, int B)
{
    extern __shared__ float sm[];
    float* s_w    = sm + OFF_W;
    float* s_wmux = sm + OFF_WMUX;
    float* s_wmuy = sm + OFF_WMUY;
    float* s_bhh  = sm + OFF_BHH;
    float* s_w5   = sm + OFF_W5;
    float* s_mux  = sm + OFF_MUX;
    float* s_muy  = sm + OFF_MUY;

    const int tid  = threadIdx.x;
    const int warp = tid >> 5, lane = tid & 31;
    const int wjb  = warp & 1;                // jb-stagger parity
    const int grp  = lane >> 3;               // 0..3: j-group within warp slice
    const int m0   = (lane & 7) * 8;          // 8 batch rows (4 f32x2 pairs)
    const int m0p  = mgap(m0);
    const int b0   = blockIdx.x * 64;
    const size_t Bs = (size_t)B;

    const uint32_t s_w_u32 = (uint32_t)__cvta_generic_to_shared(s_w);

    // ---- one-time small-weight staging ----
    for (int i = tid; i < 768; i += NTHR) {
        s_wmux[i] = Wih[(size_t)i * 386 + 384];
        s_wmuy[i] = Wih[(size_t)i * 386 + 385];
        s_bhh[i]  = bhhg[i];
    }
    for (int i = tid; i < 512; i += NTHR) s_w5[i] = Wmu[i];
    for (int i = tid; i < 768; i += NTHR) s_w5[512 + i] = Wcov[i];
    if (tid < 64) { s_mux[tid] = 0.f; s_muy[tid] = 0.f; }

    // ================= PRECOMPUTE: h0 (buf 0, gapped transposed) and gi_base ==========
    {
        const int tx4 = tid & 15, ty4 = tid >> 4;   // 16 x 16
        const int j04 = tx4 * 4, m04 = ty4 * 4;     // j-tile 4, m-tile 4
        const int m04p = mgap(m04);                  // m04 mult of 4: no gap crossing
        float* s_zhT = s_w;          // [64 k][68]
        float* s_wtp = s_w + 4352;   // [64 k][68]

        for (int jb = 0; jb < 16; ++jb) {
            ull acc[4][2];
            #pragma unroll
            for (int m = 0; m < 4; ++m) { acc[m][0] = 0ull; acc[m][1] = 0ull; }

            for (int kc = 0; kc < 6; ++kc) {
                __syncthreads();
                #pragma unroll
                for (int it = 0; it < 16; ++it) {
                    int idx = it * NTHR + tid;
                    int kk = idx & 63, rr = idx >> 6;
                    s_zhT[kk * 68 + rr] = zh[(size_t)(b0 + rr) * INDIM + kc * 64 + kk];
                    int jp = jb * 64 + rr;
                    const float* wrow = (jp < 256) ? (Wh0 + (size_t)jp * 384)
                                                   : (Wih + (size_t)(jp - 256) * 386);
                    s_wtp[kk * 68 + rr] = wrow[kc * 64 + kk];
                }
                __syncthreads();
                #pragma unroll 8
                for (int k = 0; k < 64; ++k) {
                    float4 hv = *(const float4*)&s_zhT[k * 68 + m04];
                    ull w0 = *(const ull*)&s_wtp[k * 68 + j04];
                    ull w1 = *(const ull*)&s_wtp[k * 68 + j04 + 2];
                    ull a0 = pack2(hv.x, hv.x), a1 = pack2(hv.y, hv.y);
                    ull a2 = pack2(hv.z, hv.z), a3 = pack2(hv.w, hv.w);
                    ffma2(acc[0][0], a0, w0); ffma2(acc[0][1], a0, w1);
                    ffma2(acc[1][0], a1, w0); ffma2(acc[1][1], a1, w1);
                    ffma2(acc[2][0], a2, w0); ffma2(acc[2][1], a2, w1);
                    ffma2(acc[3][0], a3, w0); ffma2(acc[3][1], a3, w1);
                }
            }
            float v[4][4];
            #pragma unroll
            for (int m = 0; m < 4; ++m) {
                unpack2(acc[m][0], v[m][0], v[m][1]);
                unpack2(acc[m][1], v[m][2], v[m][3]);
            }
            if (jb < 4) {
                #pragma unroll
                for (int jj = 0; jj < 4; ++jj) {
                    int j = jb * 64 + j04 + jj;
                    float b = bh0[j];
                    *(float4*)&sm[OFF_HT + (size_t)j * HT_STRIDE + m04p] =
                        make_float4(v[0][jj] + b, v[1][jj] + b, v[2][jj] + b, v[3][jj] + b);
                }
            } else {
                int gcol = jb * 64 - 256 + j04;
                float4 bb = *(const float4*)&bih[gcol];
                const float* bbp = (const float*)&bb;
                #pragma unroll
                for (int jj = 0; jj < 4; ++jj) {
                    *(float4*)&g_gi[(size_t)(gcol + jj) * Bs + b0 + m04] =
                        make_float4(v[0][jj] + bbp[jj], v[1][jj] + bbp[jj],
                                    v[2][jj] + bbp[jj], v[3][jj] + bbp[jj]);
                }
            }
        }
        __syncthreads();    // precompute done before W staging reuses s_w
    }

    const size_t covbase = (size_t)B * HORIZON * 2;

    // Prime per-warp W pipeline with this warp's first two chunks (its own jb order)
    issue_chunk_w(s_w_u32, Whh, wjb * 16 + 0, warp, lane);
    CPA_COMMIT();
    issue_chunk_w(s_w_u32, Whh, wjb * 16 + 1, warp, lane);
    CPA_COMMIT();

    // ================= 30-step GRU recurrence (R7 barrier scheme) =================
    int cur = 0;
    #pragma unroll 1
    for (int t = 0; t < HORIZON; ++t) {
        float* hcur = sm + OFF_HT + cur * HT_SIZE;
        float* hnxt = sm + OFF_HT + (1 - cur) * HT_SIZE;

        #pragma unroll 1
        for (int jbi = 0; jbi < 2; ++jbi) {
            const int jb  = jbi ^ wjb;                         // staggered jb order
            const int jg0 = jb * 128 + warp * 16 + grp * 4;    // lane's 4 contiguous j

            // acc[gate][j2][mpair], seeded with b_hh
            ull acc[3][4][4];
            #pragma unroll
            for (int g = 0; g < 3; ++g)
                #pragma unroll
                for (int j2 = 0; j2 < 4; ++j2) {
                    float b = s_bhh[g * 256 + jg0 + j2];
                    ull bb = pack2(b, b);
                    #pragma unroll
                    for (int mp = 0; mp < 4; ++mp) acc[g][j2][mp] = bb;
                }

            // Dependency-free L2 warm-up for the epilogue's 12 gi rows.
            #pragma unroll
            for (int j2 = 0; j2 < 4; ++j2) {
                const int j = jg0 + j2;
                asm volatile("prefetch.global.L2 [%0];"
                             :: "l"(g_gi + (size_t)(        j) * Bs + b0 + m0));
                asm volatile("prefetch.global.L2 [%0];"
                             :: "l"(g_gi + (size_t)(256 +   j) * Bs + b0 + m0));
                asm volatile("prefetch.global.L2 [%0];"
                             :: "l"(g_gi + (size_t)(512 +   j) * Bs + b0 + m0));
            }

            #pragma unroll 1
            for (int kc = 0; kc < 16; ++kc) {
                CPA_WAIT1();   // sequence element (jbi*16+kc) resident in buffer (kc&1)

                const float* wb  = s_w + (warp * 2 + (kc & 1)) * WARP_WBUF;
                const float* hch = hcur + (size_t)(kc * 16) * HT_STRIDE + m0p;

                #pragma unroll
                for (int kg = 0; kg < 4; ++kg) {
                    // 12 LDS.128: W quads for (3 gates x 4 j2), conflict-free rows
                    float4 w4[3][4];
                    #pragma unroll
                    for (int g = 0; g < 3; ++g)
                        #pragma unroll
                        for (int j2 = 0; j2 < 4; ++j2)
                            w4[g][j2] = *(const float4*)
                                &wb[(g * 16 + j2 * 4 + grp) * W_ROWPAD + kg * 4];
                    #pragma unroll
                    for (int kk = 0; kk < 4; ++kk) {
                        const float* hr = hch + (size_t)(kg * 4 + kk) * HT_STRIDE;
                        ulonglong2 q0 = *(const ulonglong2*)hr;        // m pairs 0..1
                        ulonglong2 q1 = *(const ulonglong2*)(hr + 4);  // m pairs 2..3
                        #pragma unroll
                        for (int g = 0; g < 3; ++g)
                            #pragma unroll
                            for (int j2 = 0; j2 < 4; ++j2) {
                                float ws = ((const float*)&w4[g][j2])[kk];
                                ull d = pack2(ws, ws);
                                ffma2(acc[g][j2][0], q0.x, d);
                                ffma2(acc[g][j2][1], q0.y, d);
                                ffma2(acc[g][j2][2], q1.x, d);
                                ffma2(acc[g][j2][3], q1.y, d);
                            }
                    }
                }
                // Issue sequence element s+2 (wraps into next step's identical order).
                {
                    int s2 = jbi * 16 + kc + 2;                 // up to 33
                    int jb2 = ((s2 >> 4) & 1) ^ wjb;
                    int c2  = jb2 * 16 + (s2 & 15);
                    issue_chunk_w(s_w_u32, Whh, c2, warp, lane);
                    CPA_COMMIT();
                }
            }

            // ---- gate epilogue: 4 j x 8 m GRU cells, pre-activations in f32x2 ----
            // mu pairs for this lane's 8 m (published by prev step's mu/cov, fenced
            // by the barrier at end of the previous step).
            ulonglong2 mxq0 = *(const ulonglong2*)&s_mux[m0];
            ulonglong2 mxq1 = *(const ulonglong2*)&s_mux[m0 + 4];
            ulonglong2 myq0 = *(const ulonglong2*)&s_muy[m0];
            ulonglong2 myq1 = *(const ulonglong2*)&s_muy[m0 + 4];
            ull mxp[4] = {mxq0.x, mxq0.y, mxq1.x, mxq1.y};
            ull myp[4] = {myq0.x, myq0.y, myq1.x, myq1.y};

            #pragma unroll
            for (int j2 = 0; j2 < 4; ++j2) {
                const int j = jg0 + j2;
                // gi loads as packed f32x2 pairs (16B quads)
                const float* pr = g_gi + (size_t)(        j) * Bs + b0 + m0;
                const float* pz = g_gi + (size_t)(256 +   j) * Bs + b0 + m0;
                const float* pn = g_gi + (size_t)(512 +   j) * Bs + b0 + m0;
                ulonglong2 grq0 = *(const ulonglong2*)pr, grq1 = *(const ulonglong2*)(pr + 4);
                ulonglong2 gzq0 = *(const ulonglong2*)pz, gzq1 = *(const ulonglong2*)(pz + 4);
                ulonglong2 gnq0 = *(const ulonglong2*)pn, gnq1 = *(const ulonglong2*)(pn + 4);
                ull gRp[4] = {grq0.x, grq0.y, grq1.x, grq1.y};
                ull gZp[4] = {gzq0.x, gzq0.y, gzq1.x, gzq1.y};
                ull gNp[4] = {gnq0.x, gnq0.y, gnq1.x, gnq1.y};

                ull wxr2 = pack2(s_wmux[j], s_wmux[j]);
                ull wxz2 = pack2(s_wmux[256 + j], s_wmux[256 + j]);
                ull wxn2 = pack2(s_wmux[512 + j], s_wmux[512 + j]);
                ull wyr2 = pack2(s_wmuy[j], s_wmuy[j]);
                ull wyz2 = pack2(s_wmuy[256 + j], s_wmuy[256 + j]);
                ull wyn2 = pack2(s_wmuy[512 + j], s_wmuy[512 + j]);

                // Pre-activations per m-pair: pre = gi + mx*wx + my*wy (+ acc for r/z)
                float fr[8], fz[8], fn[8];
                #pragma unroll
                for (int mp = 0; mp < 4; ++mp) {
                    ull ar = add2v(gRp[mp], acc[0][j2][mp]);
                    ar = ffma2v(mxp[mp], wxr2, ar);
                    ar = ffma2v(myp[mp], wyr2, ar);
                    unpack2(ar, fr[2*mp], fr[2*mp+1]);

                    ull az = add2v(gZp[mp], acc[1][j2][mp]);
                    az = ffma2v(mxp[mp], wxz2, az);
                    az = ffma2v(myp[mp], wyz2, az);
                    unpack2(az, fz[2*mp], fz[2*mp+1]);

                    // n gate: gi-part only (acc[2] = hidden part, multiplied by r later)
                    ull an = ffma2v(mxp[mp], wxn2, gNp[mp]);
                    an = ffma2v(myp[mp], wyn2, an);
                    unpack2(an, fn[2*mp], fn[2*mp+1]);
                }
                float hn[8];
                #pragma unroll
                for (int mp = 0; mp < 4; ++mp)
                    unpack2(acc[2][j2][mp], hn[2*mp], hn[2*mp+1]);

                const float* hp = &hcur[(size_t)j * HT_STRIDE + m0p];
                float4 o0 = *(const float4*)hp;
                float4 o1 = *(const float4*)(hp + 4);
                float ho[8] = {o0.x,o0.y,o0.z,o0.w,o1.x,o1.y,o1.z,o1.w};

                float hnew[8];
                #pragma unroll
                for (int m = 0; m < 8; ++m) {
                    float r  = sig_t(fr[m]);
                    float z  = sig_t(fz[m]);
                    float n  = tanha(fn[m] + r * hn[m]);
                    hnew[m] = (1.f - z) * n + z * ho[m];
                }
                float* hq = &hnxt[(size_t)j * HT_STRIDE + m0p];
                *(float4*)hq       = make_float4(hnew[0], hnew[1], hnew[2], hnew[3]);
                *(float4*)(hq + 4) = make_float4(hnew[4], hnew[5], hnew[6], hnew[7]);
            }
        } // jbi

        __syncthreads();   // hnxt complete (both jb halves, all warps)

        // ---- mu / cov: 5 outputs x 32 m-pairs = 160 tasks, float2 column loads ----
        if (tid < 160) {
            int o = tid >> 5; int mp = tid & 31;
            int m = mp * 2;
            const float* wrow = &s_w5[o * 256];
            const float* hc = hnxt + mgap(m);
            float2 A0 = make_float2(0.f, 0.f), A1 = make_float2(0.f, 0.f);
            float2 A2 = make_float2(0.f, 0.f), A3 = make_float2(0.f, 0.f);
            #pragma unroll 4
            for (int k = 0; k < 256; k += 4) {
                float2 v0 = *(const float2*)&hc[(size_t)(k    ) * HT_STRIDE];
                float2 v1 = *(const float2*)&hc[(size_t)(k + 1) * HT_STRIDE];
                float2 v2 = *(const float2*)&hc[(size_t)(k + 2) * HT_STRIDE];
                float2 v3 = *(const float2*)&hc[(size_t)(k + 3) * HT_STRIDE];
                A0.x += v0.x * wrow[k    ];  A0.y += v0.y * wrow[k    ];
                A1.x += v1.x * wrow[k + 1];  A1.y += v1.y * wrow[k + 1];
                A2.x += v2.x * wrow[k + 2];  A2.y += v2.y * wrow[k + 2];
                A3.x += v3.x * wrow[k + 3];  A3.y += v3.y * wrow[k + 3];
            }
            float accA = (A0.x + A1.x) + (A2.x + A3.x);
            float accB = (A0.y + A1.y) + (A2.y + A3.y);
            #pragma unroll
            for (int h2 = 0; h2 < 2; ++h2) {
                float acc5 = h2 ? accB : accA;
                int mm = m + h2;
                size_t idx2 = ((size_t)(b0 + mm) * HORIZON + t);
                if (o == 0) {
                    float vv = acc5 + bmu[0]; out[idx2 * 2]     = vv; s_mux[mm] = vv;
                } else if (o == 1) {
                    float vv = acc5 + bmu[1]; out[idx2 * 2 + 1] = vv; s_muy[mm] = vv;
                } else if (o == 2) {
                    float vv = fminf(fmaxf(acc5 + bcov[0], 0.2f), 1.0f);
                    out[covbase + idx2 * 4]     = vv;
                } else if (o == 3) {
                    float vv = fminf(fmaxf(acc5 + bcov[1], -0.1f), 0.1f);
                    out[covbase + idx2 * 4 + 1] = vv;
                    out[covbase + idx2 * 4 + 2] = vv;
                } else {
                    float vv = fminf(fmaxf(acc5 + bcov[2], 0.2f), 1.0f);
                    out[covbase + idx2 * 4 + 3] = vv;
                }
            }
        }
        __syncthreads();   // s_mux/s_muy published before next step's epilogues read
        cur ^= 1;
    }

    CPA_WAIT0();   // drain speculative prefetches
}

extern "C" void kernel_launch(void* const* d_in, const int* in_sizes, int n_in,
                              void* d_out, int out_size) {
    const float* zh   = (const float*)d_in[0];
    const float* Wh0  = (const float*)d_in[1];
    const float* bh0  = (const float*)d_in[2];
    const float* Wih  = (const float*)d_in[3];
    const float* bih  = (const float*)d_in[4];
    const float* Whh  = (const float*)d_in[5];
    const float* bhh  = (const float*)d_in[6];
    const float* Wmu  = (const float*)d_in[7];
    const float* bmu  = (const float*)d_in[8];
    const float* Wcov = (const float*)d_in[9];
    const float* bcov = (const float*)d_in[10];
    float* out = (float*)d_out;

    int B = in_sizes[0] / INDIM;
    cudaFuncSetAttribute(gru_decoder_kernel,
                         cudaFuncAttributeMaxDynamicSharedMemorySize, SMEM_FLOATS * 4);
    gru_decoder_kernel<<<B / 64, NTHR, SMEM_FLOATS * 4>>>(
        zh, Wh0, bh0, Wih, bih, Whh, bhh, Wmu, bmu, Wcov, bcov, out, B);
}

// round 17
// speedup vs baseline: 1.0979x; 1.0103x over previous
#include <cuda_runtime.h>
#include <cstdint>

#define HORIZON 30
#define INDIM   384
#define BMAX    65536

typedef unsigned long long ull;

// gi_base scratch, TRANSPOSED layout: [row = gate*256 + j][B] fp32 (192 MB).
__device__ float g_gi[(size_t)768 * BMAX];

__device__ __forceinline__ ull pack2(float lo, float hi) {
    ull r; asm("mov.b64 %0, {%1, %2};" : "=l"(r) : "f"(lo), "f"(hi)); return r;
}
__device__ __forceinline__ void ffma2(ull& d, ull a, ull b) {
    asm("fma.rn.f32x2 %0, %1, %2, %0;" : "+l"(d) : "l"(a), "l"(b));
}
__device__ __forceinline__ ull ffma2v(ull a, ull b, ull c) {
    ull d; asm("fma.rn.f32x2 %0, %1, %2, %3;" : "=l"(d) : "l"(a), "l"(b), "l"(c)); return d;
}
__device__ __forceinline__ ull add2v(ull a, ull b) {
    ull d; asm("add.rn.f32x2 %0, %1, %2;" : "=l"(d) : "l"(a), "l"(b)); return d;
}
__device__ __forceinline__ void unpack2(ull v, float& lo, float& hi) {
    asm("mov.b64 {%0, %1}, %2;" : "=f"(lo), "=f"(hi) : "l"(v));
}
// Native MUFU tanh: 1 op, max err ~2^-11; recurrence contractive (measured 4.1e-6).
__device__ __forceinline__ float tanha(float x) {
    float y; asm("tanh.approx.f32 %0, %1;" : "=f"(y) : "f"(x)); return y;
}
__device__ __forceinline__ float sig_t(float x) {
    return fmaf(0.5f, tanha(0.5f * x), 0.5f);
}
__device__ __forceinline__ void cpa16(uint32_t s, const void* g) {
    asm volatile("cp.async.cg.shared.global [%0], [%1], 16;" :: "r"(s), "l"(g));
}
#define CPA_COMMIT() asm volatile("cp.async.commit_group;")
#define CPA_WAIT1()  asm volatile("cp.async.wait_group 1;")
#define CPA_WAIT0()  asm volatile("cp.async.wait_group 0;")

// ---------------- shared memory layout (floats) ----------------
// h rows: 64 floats of data with a 4-float gap after m=31; stride 72.
#define HT_STRIDE 72
#define HT_SIZE   (256 * HT_STRIDE)          // 18432
#define OFF_HT    0                           // 2 ping-pong buffers
#define OFF_W     (2 * HT_SIZE)              // 36864
#define W_ROWPAD  20
#define WARP_WBUF (48 * W_ROWPAD)            // 960 floats: 48 rows x 16 k
#define W_REGION  (8 * 2 * WARP_WBUF)        // 15360 floats (8 warps x 2 buffers)
#define OFF_WMUX  (OFF_W + W_REGION)         // 52224
#define OFF_WMUY  (OFF_WMUX + 768)
#define OFF_BHH   (OFF_WMUY + 768)
#define OFF_W5    (OFF_BHH + 768)
#define OFF_MUX   (OFF_W5 + 1280)
#define OFF_MUY   (OFF_MUX + 64)
#define SMEM_FLOATS (OFF_MUY + 64)           // 55936 floats = 223744 B

#define NTHR 256

__device__ __forceinline__ int mgap(int m) { return m + ((m >> 5) << 2); }

__global__ void __launch_bounds__(NTHR, 1)
gru_decoder_kernel(const float* __restrict__ zh,  const float* __restrict__ Wh0,
                   const float* __restrict__ bh0, const float* __restrict__ Wih,
                   const float* __restrict__ bih, const float* __restrict__ Whh,
                   const float* __restrict__ bhhg,const float* __restrict__ Wmu,
                   const float* __restrict__ bmu, const float* __restrict__ Wcov,
                   const float* __restrict__ bcov,float* __restrict__ out, int B)
{
    extern __shared__ float sm[];
    float* s_w    = sm + OFF_W;
    float* s_wmux = sm + OFF_WMUX;
    float* s_wmuy = sm + OFF_WMUY;
    float* s_bhh  = sm + OFF_BHH;
    float* s_w5   = sm + OFF_W5;
    float* s_mux  = sm + OFF_MUX;
    float* s_muy  = sm + OFF_MUY;

    const int tid  = threadIdx.x;
    const int warp = tid >> 5, lane = tid & 31;
    const int wjb  = warp & 1;                // jb-stagger parity
    const int grp  = lane >> 3;               // 0..3: j-group within warp slice
    const int m0   = (lane & 7) * 8;          // 8 batch rows (4 f32x2 pairs)
    const int m0p  = mgap(m0);
    const int b0   = blockIdx.x * 64;
    const size_t Bs = (size_t)B;

    const uint32_t s_w_u32 = (uint32_t)__cvta_generic_to_shared(s_w);

    // ---- one-time small-weight staging ----
    for (int i = tid; i < 768; i += NTHR) {
        s_wmux[i] = Wih[(size_t)i * 386 + 384];
        s_wmuy[i] = Wih[(size_t)i * 386 + 385];
        s_bhh[i]  = bhhg[i];
    }
    for (int i = tid; i < 512; i += NTHR) s_w5[i] = Wmu[i];
    for (int i = tid; i < 768; i += NTHR) s_w5[512 + i] = Wcov[i];
    if (tid < 64) { s_mux[tid] = 0.f; s_muy[tid] = 0.f; }

    // ================= PRECOMPUTE: h0 (buf 0, gapped transposed) and gi_base ==========
    {
        const int tx4 = tid & 15, ty4 = tid >> 4;   // 16 x 16
        const int j04 = tx4 * 4, m04 = ty4 * 4;     // j-tile 4, m-tile 4
        const int m04p = mgap(m04);                  // m04 mult of 4: no gap crossing
        float* s_zhT = s_w;          // [64 k][68]
        float* s_wtp = s_w + 4352;   // [64 k][68]

        for (int jb = 0; jb < 16; ++jb) {
            ull acc[4][2];
            #pragma unroll
            for (int m = 0; m < 4; ++m) { acc[m][0] = 0ull; acc[m][1] = 0ull; }

            for (int kc = 0; kc < 6; ++kc) {
                __syncthreads();
                #pragma unroll
                for (int it = 0; it < 16; ++it) {
                    int idx = it * NTHR + tid;
                    int kk = idx & 63, rr = idx >> 6;
                    s_zhT[kk * 68 + rr] = zh[(size_t)(b0 + rr) * INDIM + kc * 64 + kk];
                    int jp = jb * 64 + rr;
                    const float* wrow = (jp < 256) ? (Wh0 + (size_t)jp * 384)
                                                   : (Wih + (size_t)(jp - 256) * 386);
                    s_wtp[kk * 68 + rr] = wrow[kc * 64 + kk];
                }
                __syncthreads();
                #pragma unroll 8
                for (int k = 0; k < 64; ++k) {
                    float4 hv = *(const float4*)&s_zhT[k * 68 + m04];
                    ull w0 = *(const ull*)&s_wtp[k * 68 + j04];
                    ull w1 = *(const ull*)&s_wtp[k * 68 + j04 + 2];
                    ull a0 = pack2(hv.x, hv.x), a1 = pack2(hv.y, hv.y);
                    ull a2 = pack2(hv.z, hv.z), a3 = pack2(hv.w, hv.w);
                    ffma2(acc[0][0], a0, w0); ffma2(acc[0][1], a0, w1);
                    ffma2(acc[1][0], a1, w0); ffma2(acc[1][1], a1, w1);
                    ffma2(acc[2][0], a2, w0); ffma2(acc[2][1], a2, w1);
                    ffma2(acc[3][0], a3, w0); ffma2(acc[3][1], a3, w1);
                }
            }
            float v[4][4];
            #pragma unroll
            for (int m = 0; m < 4; ++m) {
                unpack2(acc[m][0], v[m][0], v[m][1]);
                unpack2(acc[m][1], v[m][2], v[m][3]);
            }
            if (jb < 4) {
                #pragma unroll
                for (int jj = 0; jj < 4; ++jj) {
                    int j = jb * 64 + j04 + jj;
                    float b = bh0[j];
                    *(float4*)&sm[OFF_HT + (size_t)j * HT_STRIDE + m04p] =
                        make_float4(v[0][jj] + b, v[1][jj] + b, v[2][jj] + b, v[3][jj] + b);
                }
            } else {
                int gcol = jb * 64 - 256 + j04;
                float4 bb = *(const float4*)&bih[gcol];
                const float* bbp = (const float*)&bb;
                #pragma unroll
                for (int jj = 0; jj < 4; ++jj) {
                    *(float4*)&g_gi[(size_t)(gcol + jj) * Bs + b0 + m04] =
                        make_float4(v[0][jj] + bbp[jj], v[1][jj] + bbp[jj],
                                    v[2][jj] + bbp[jj], v[3][jj] + bbp[jj]);
                }
            }
        }
        __syncthreads();    // precompute done before W staging reuses s_w
    }

    const size_t covbase = (size_t)B * HORIZON * 2;

    // ---- Hoisted W-staging addressing (lane-invariant across the whole run) ----
    // Task o: buffer row r = o*8 + lane>>2, quad q = lane&3.
    // Global: Whh row (g*256 + jb*128 + warp*16 + jloc), jloc = (rl&3)*4 + (rl>>2).
    const float* wg_base[6];   // jb=0, kc=0 pointer per task
    uint32_t     ws_dst[6];    // parity-0 smem dst per task
    #pragma unroll
    for (int o = 0; o < 6; ++o) {
        int t = o * 32 + lane;
        int r = t >> 2, q = t & 3;
        int g = r >> 4, rl = r & 15;
        int jloc = (rl & 3) * 4 + (rl >> 2);
        wg_base[o] = Whh + (size_t)(g * 256 + warp * 16 + jloc) * 256 + q * 4;
        ws_dst[o]  = s_w_u32 + (uint32_t)((warp * 2) * WARP_WBUF * 4)
                             + (uint32_t)((r * W_ROWPAD + q * 4) * 4);
    }
    // Issue chunk c (jb = (c>>4)&1, kc = c&15, parity = c&1) using hoisted bases.
    #define ISSUE_CHUNK(c_) do {                                               \
        int c__ = (c_);                                                        \
        uint32_t goff__ = (uint32_t)(((c__ >> 4) & 1) * (128 * 256 * 4)        \
                                     + (c__ & 15) * 64);                       \
        uint32_t soff__ = (uint32_t)((c__ & 1) * (WARP_WBUF * 4));             \
        _Pragma("unroll")                                                      \
        for (int o__ = 0; o__ < 6; ++o__)                                      \
            cpa16(ws_dst[o__] + soff__,                                        \
                  (const char*)wg_base[o__] + goff__);                         \
        CPA_COMMIT();                                                          \
    } while (0)

    // Prime per-warp W pipeline with this warp's first two chunks (its own jb order)
    ISSUE_CHUNK(wjb * 16 + 0);
    ISSUE_CHUNK(wjb * 16 + 1);

    // ================= 30-step GRU recurrence (R7 barrier scheme) =================
    int cur = 0;
    #pragma unroll 1
    for (int t = 0; t < HORIZON; ++t) {
        float* hcur = sm + OFF_HT + cur * HT_SIZE;
        float* hnxt = sm + OFF_HT + (1 - cur) * HT_SIZE;

        #pragma unroll 1
        for (int jbi = 0; jbi < 2; ++jbi) {
            const int jb  = jbi ^ wjb;                         // staggered jb order
            const int jg0 = jb * 128 + warp * 16 + grp * 4;    // lane's 4 contiguous j

            // acc[gate][j2][mpair], seeded with b_hh
            ull acc[3][4][4];
            #pragma unroll
            for (int g = 0; g < 3; ++g)
                #pragma unroll
                for (int j2 = 0; j2 < 4; ++j2) {
                    float b = s_bhh[g * 256 + jg0 + j2];
                    ull bb = pack2(b, b);
                    #pragma unroll
                    for (int mp = 0; mp < 4; ++mp) acc[g][j2][mp] = bb;
                }

            // Dependency-free L2 warm-up for the epilogue's 12 gi rows.
            #pragma unroll
            for (int j2 = 0; j2 < 4; ++j2) {
                const int j = jg0 + j2;
                asm volatile("prefetch.global.L2 [%0];"
                             :: "l"(g_gi + (size_t)(        j) * Bs + b0 + m0));
                asm volatile("prefetch.global.L2 [%0];"
                             :: "l"(g_gi + (size_t)(256 +   j) * Bs + b0 + m0));
                asm volatile("prefetch.global.L2 [%0];"
                             :: "l"(g_gi + (size_t)(512 +   j) * Bs + b0 + m0));
            }

            #pragma unroll 1
            for (int kc = 0; kc < 16; ++kc) {
                CPA_WAIT1();   // sequence element (jbi*16+kc) resident in buffer (kc&1)

                const float* wb  = s_w + (warp * 2 + (kc & 1)) * WARP_WBUF;
                const float* hch = hcur + (size_t)(kc * 16) * HT_STRIDE + m0p;

                #pragma unroll
                for (int kg = 0; kg < 4; ++kg) {
                    // 12 LDS.128: W quads for (3 gates x 4 j2), conflict-free rows
                    float4 w4[3][4];
                    #pragma unroll
                    for (int g = 0; g < 3; ++g)
                        #pragma unroll
                        for (int j2 = 0; j2 < 4; ++j2)
                            w4[g][j2] = *(const float4*)
                                &wb[(g * 16 + j2 * 4 + grp) * W_ROWPAD + kg * 4];
                    #pragma unroll
                    for (int kk = 0; kk < 4; ++kk) {
                        const float* hr = hch + (size_t)(kg * 4 + kk) * HT_STRIDE;
                        ulonglong2 q0 = *(const ulonglong2*)hr;        // m pairs 0..1
                        ulonglong2 q1 = *(const ulonglong2*)(hr + 4);  // m pairs 2..3
                        #pragma unroll
                        for (int g = 0; g < 3; ++g)
                            #pragma unroll
                            for (int j2 = 0; j2 < 4; ++j2) {
                                float ws = ((const float*)&w4[g][j2])[kk];
                                ull d = pack2(ws, ws);
                                ffma2(acc[g][j2][0], q0.x, d);
                                ffma2(acc[g][j2][1], q0.y, d);
                                ffma2(acc[g][j2][2], q1.x, d);
                                ffma2(acc[g][j2][3], q1.y, d);
                            }
                    }
                }
                // Issue sequence element s+2 (wraps into next step's identical order).
                {
                    int s2 = jbi * 16 + kc + 2;                 // up to 33
                    int jb2 = ((s2 >> 4) & 1) ^ wjb;
                    ISSUE_CHUNK(jb2 * 16 + (s2 & 15));
                }
            }

            // ---- gate epilogue: 4 j x 8 m GRU cells, pre-activations in f32x2 ----
            ulonglong2 mxq0 = *(const ulonglong2*)&s_mux[m0];
            ulonglong2 mxq1 = *(const ulonglong2*)&s_mux[m0 + 4];
            ulonglong2 myq0 = *(const ulonglong2*)&s_muy[m0];
            ulonglong2 myq1 = *(const ulonglong2*)&s_muy[m0 + 4];
            ull mxp[4] = {mxq0.x, mxq0.y, mxq1.x, mxq1.y};
            ull myp[4] = {myq0.x, myq0.y, myq1.x, myq1.y};

            #pragma unroll
            for (int j2 = 0; j2 < 4; ++j2) {
                const int j = jg0 + j2;
                const float* pr = g_gi + (size_t)(        j) * Bs + b0 + m0;
                const float* pz = g_gi + (size_t)(256 +   j) * Bs + b0 + m0;
                const float* pn = g_gi + (size_t)(512 +   j) * Bs + b0 + m0;
                ulonglong2 grq0 = *(const ulonglong2*)pr, grq1 = *(const ulonglong2*)(pr + 4);
                ulonglong2 gzq0 = *(const ulonglong2*)pz, gzq1 = *(const ulonglong2*)(pz + 4);
                ulonglong2 gnq0 = *(const ulonglong2*)pn, gnq1 = *(const ulonglong2*)(pn + 4);
                ull gRp[4] = {grq0.x, grq0.y, grq1.x, grq1.y};
                ull gZp[4] = {gzq0.x, gzq0.y, gzq1.x, gzq1.y};
                ull gNp[4] = {gnq0.x, gnq0.y, gnq1.x, gnq1.y};

                ull wxr2 = pack2(s_wmux[j], s_wmux[j]);
                ull wxz2 = pack2(s_wmux[256 + j], s_wmux[256 + j]);
                ull wxn2 = pack2(s_wmux[512 + j], s_wmux[512 + j]);
                ull wyr2 = pack2(s_wmuy[j], s_wmuy[j]);
                ull wyz2 = pack2(s_wmuy[256 + j], s_wmuy[256 + j]);
                ull wyn2 = pack2(s_wmuy[512 + j], s_wmuy[512 + j]);

                float fr[8], fz[8], fn[8];
                #pragma unroll
                for (int mp = 0; mp < 4; ++mp) {
                    ull ar = add2v(gRp[mp], acc[0][j2][mp]);
                    ar = ffma2v(mxp[mp], wxr2, ar);
                    ar = ffma2v(myp[mp], wyr2, ar);
                    unpack2(ar, fr[2*mp], fr[2*mp+1]);

                    ull az = add2v(gZp[mp], acc[1][j2][mp]);
                    az = ffma2v(mxp[mp], wxz2, az);
                    az = ffma2v(myp[mp], wyz2, az);
                    unpack2(az, fz[2*mp], fz[2*mp+1]);

                    ull an = ffma2v(mxp[mp], wxn2, gNp[mp]);
                    an = ffma2v(myp[mp], wyn2, an);
                    unpack2(an, fn[2*mp], fn[2*mp+1]);
                }
                float hn[8];
                #pragma unroll
                for (int mp = 0; mp < 4; ++mp)
                    unpack2(acc[2][j2][mp], hn[2*mp], hn[2*mp+1]);

                const float* hp = &hcur[(size_t)j * HT_STRIDE + m0p];
                float4 o0 = *(const float4*)hp;
                float4 o1 = *(const float4*)(hp + 4);
                float ho[8] = {o0.x,o0.y,o0.z,o0.w,o1.x,o1.y,o1.z,o1.w};

                float hnew[8];
                #pragma unroll
                for (int m = 0; m < 8; ++m) {
                    float r  = sig_t(fr[m]);
                    float z  = sig_t(fz[m]);
                    float n  = tanha(fn[m] + r * hn[m]);
                    hnew[m] = (1.f - z) * n + z * ho[m];
                }
                float* hq = &hnxt[(size_t)j * HT_STRIDE + m0p];
                *(float4*)hq       = make_float4(hnew[0], hnew[1], hnew[2], hnew[3]);
                *(float4*)(hq + 4) = make_float4(hnew[4], hnew[5], hnew[6], hnew[7]);
            }
        } // jbi

        __syncthreads();   // hnxt complete (both jb halves, all warps)

        // ---- mu / cov: 5 outputs x 32 m-pairs = 160 tasks, float2 column loads ----
        if (tid < 160) {
            int o = tid >> 5; int mp = tid & 31;
            int m = mp * 2;
            const float* wrow = &s_w5[o * 256];
            const float* hc = hnxt + mgap(m);
            float2 A0 = make_float2(0.f, 0.f), A1 = make_float2(0.f, 0.f);
            float2 A2 = make_float2(0.f, 0.f), A3 = make_float2(0.f, 0.f);
            #pragma unroll 4
            for (int k = 0; k < 256; k += 4) {
                float2 v0 = *(const float2*)&hc[(size_t)(k    ) * HT_STRIDE];
                float2 v1 = *(const float2*)&hc[(size_t)(k + 1) * HT_STRIDE];
                float2 v2 = *(const float2*)&hc[(size_t)(k + 2) * HT_STRIDE];
                float2 v3 = *(const float2*)&hc[(size_t)(k + 3) * HT_STRIDE];
                A0.x += v0.x * wrow[k    ];  A0.y += v0.y * wrow[k    ];
                A1.x += v1.x * wrow[k + 1];  A1.y += v1.y * wrow[k + 1];
                A2.x += v2.x * wrow[k + 2];  A2.y += v2.y * wrow[k + 2];
                A3.x += v3.x * wrow[k + 3];  A3.y += v3.y * wrow[k + 3];
            }
            float accA = (A0.x + A1.x) + (A2.x + A3.x);
            float accB = (A0.y + A1.y) + (A2.y + A3.y);
            #pragma unroll
            for (int h2 = 0; h2 < 2; ++h2) {
                float acc5 = h2 ? accB : accA;
                int mm = m + h2;
                size_t idx2 = ((size_t)(b0 + mm) * HORIZON + t);
                if (o == 0) {
                    float vv = acc5 + bmu[0]; out[idx2 * 2]     = vv; s_mux[mm] = vv;
                } else if (o == 1) {
                    float vv = acc5 + bmu[1]; out[idx2 * 2 + 1] = vv; s_muy[mm] = vv;
                } else if (o == 2) {
                    float vv = fminf(fmaxf(acc5 + bcov[0], 0.2f), 1.0f);
                    out[covbase + idx2 * 4]     = vv;
                } else if (o == 3) {
                    float vv = fminf(fmaxf(acc5 + bcov[1], -0.1f), 0.1f);
                    out[covbase + idx2 * 4 + 1] = vv;
                    out[covbase + idx2 * 4 + 2] = vv;
                } else {
                    float vv = fminf(fmaxf(acc5 + bcov[2], 0.2f), 1.0f);
                    out[covbase + idx2 * 4 + 3] = vv;
                }
            }
        }
        __syncthreads();   // s_mux/s_muy published before next step's epilogues read
        cur ^= 1;
    }

    CPA_WAIT0();   // drain speculative prefetches
    #undef ISSUE_CHUNK
}

extern "C" void kernel_launch(void* const* d_in, const int* in_sizes, int n_in,
                              void* d_out, int out_size) {
    const float* zh   = (const float*)d_in[0];
    const float* Wh0  = (const float*)d_in[1];
    const float* bh0  = (const float*)d_in[2];
    const float* Wih  = (const float*)d_in[3];
    const float* bih  = (const float*)d_in[4];
    const float* Whh  = (const float*)d_in[5];
    const float* bhh  = (const float*)d_in[6];
    const float* Wmu  = (const float*)d_in[7];
    const float* bmu  = (const float*)d_in[8];
    const float* Wcov = (const float*)d_in[9];
    const float* bcov = (const float*)d_in[10];
    float* out = (float*)d_out;

    int B = in_sizes[0] / INDIM;
    cudaFuncSetAttribute(gru_decoder_kernel,
                         cudaFuncAttributeMaxDynamicSharedMemorySize, SMEM_FLOATS * 4);
    gru_decoder_kernel<<<B / 64, NTHR, SMEM_FLOATS * 4>>>(
        zh, Wh0, bh0, Wih, bih, Whh, bhh, Wmu, bmu, Wcov, bcov, out, B);
}